// round 1
// baseline (speedup 1.0000x reference)
#include <cuda_runtime.h>
#include <math.h>

// ---------------- problem constants ----------------
#define NQ 1024     // queries
#define ND 200000   // data points
#define NF 64       // features
#define NK 32       // neighbors
#define NC 16       // gate channels
#define NH 128      // hidden

// ---------------- K1 tiling ----------------
#define MT 128          // queries per CTA
#define NT 128          // points per tile
#define NSLICES 74
#define SLICE_LEN 2703  // 74*2703 = 200022 >= 200000
#define THREADS 256
#define QPAD 132        // smem row pad (mult of 4 for float4, odd-ish banks)
#define BUFCAP 4096

#define BIGV 3.0e38f

// ---------------- scratch (static device globals; no dynamic alloc) ----------------
__device__ float g_xx[ND];
__device__ float g_cval[(size_t)NQ * NSLICES * NK];
__device__ int   g_cidx[(size_t)NQ * NSLICES * NK];
__device__ int   g_topk[NQ * NK];

// ============================================================
// K0: squared norms of X_data rows
// ============================================================
__global__ void sqnorm_kernel(const float* __restrict__ Xd) {
    int r = blockIdx.x * 64 + (threadIdx.x >> 2);
    int part = threadIdx.x & 3;
    if (r >= ND) return;
    const float4* row = (const float4*)(Xd + (size_t)r * NF);
    float s = 0.f;
#pragma unroll
    for (int l = 0; l < 4; l++) {
        float4 v = row[part + l * 4];
        s += v.x * v.x + v.y * v.y + v.z * v.z + v.w * v.w;
    }
    s += __shfl_xor_sync(0xffffffffu, s, 1);
    s += __shfl_xor_sync(0xffffffffu, s, 2);
    if (part == 0) g_xx[r] = s;
}

// ============================================================
// K1: fused score GEMM + per-query top-32 within an N-slice
// score(q,n) = ||X_n||^2 - 2 x_q . X_n   (same order as d2)
// ============================================================
__global__ void knn_kernel(const float* __restrict__ xq, const float* __restrict__ Xd) {
    extern __shared__ float smem[];
    float*    Qs     = smem;                         // 64*QPAD
    float*    Xs     = Qs + 64 * QPAD;               // 64*QPAD
    float*    Xxs    = Xs + 64 * QPAD;               // NT
    float*    topv   = Xxs + NT;                     // MT*NK
    float*    thrS   = topv + MT * NK;               // MT
    float*    bufv   = thrS + MT;                    // BUFCAP
    int*      topi   = (int*)(bufv + BUFCAP);        // MT*NK
    unsigned* bufp   = (unsigned*)(topi + MT * NK);  // BUFCAP
    int*      s_count = (int*)(bufp + BUFCAP);
    int*      s_flag  = s_count + 1;

    const int tid   = threadIdx.x;
    const int lane  = tid & 31;
    const int w     = tid >> 5;       // warp id, owns queries [16w, 16w+16)
    const int mtile = blockIdx.x;
    const int slice = blockIdx.y;

    // load Q tile (transposed to k-major)
    for (int i = tid; i < MT * NF; i += THREADS) {
        int q = i >> 6, f = i & 63;
        Qs[f * QPAD + q] = xq[(size_t)(mtile * MT + q) * NF + f];
    }
    for (int i = tid; i < MT * NK; i += THREADS) { topv[i] = BIGV; topi[i] = 0x7FFFFFFF; }
    for (int i = tid; i < MT; i += THREADS) thrS[i] = BIGV;
    if (tid == 0) { *s_count = 0; *s_flag = 0; }
    __syncthreads();

    const int ty = tid >> 4, tx = tid & 15;
    const int qb = ty * 8, nb = tx * 8;
    const int s_begin = slice * SLICE_LEN;
    const int s_end   = (s_begin + SLICE_LEN < ND) ? (s_begin + SLICE_LEN) : ND;

    for (int t0 = s_begin; t0 < s_end; t0 += NT) {
        // load X tile (transposed to k-major), zero-pad tail
        for (int i = tid; i < NT * NF; i += THREADS) {
            int nl = i >> 6, f = i & 63;
            int n = t0 + nl;
            Xs[f * QPAD + nl] = (n < s_end) ? Xd[(size_t)n * NF + f] : 0.f;
        }
        if (tid < NT) {
            int n = t0 + tid;
            Xxs[tid] = (n < s_end) ? g_xx[n] : BIGV;
        }
        __syncthreads();

        // 8x8 register tile GEMM over K=64
        float acc[8][8];
#pragma unroll
        for (int i = 0; i < 8; i++)
#pragma unroll
            for (int j = 0; j < 8; j++) acc[i][j] = 0.f;

#pragma unroll 2
        for (int k = 0; k < NF; k++) {
            float4 qa = *(const float4*)(Qs + k * QPAD + qb);
            float4 qc = *(const float4*)(Qs + k * QPAD + qb + 4);
            float4 xa = *(const float4*)(Xs + k * QPAD + nb);
            float4 xc = *(const float4*)(Xs + k * QPAD + nb + 4);
            float qv[8] = {qa.x, qa.y, qa.z, qa.w, qc.x, qc.y, qc.z, qc.w};
            float xv[8] = {xa.x, xa.y, xa.z, xa.w, xc.x, xc.y, xc.z, xc.w};
#pragma unroll
            for (int i = 0; i < 8; i++)
#pragma unroll
                for (int j = 0; j < 8; j++) acc[i][j] += qv[i] * xv[j];
        }

        float xxr[8];
#pragma unroll
        for (int j = 0; j < 8; j++) xxr[j] = Xxs[nb + j];

        // candidate push + drain with guaranteed-progress retry
        unsigned long long pend = ~0ull;
        while (true) {
            bool bufFull = false;
#pragma unroll
            for (int i = 0; i < 8; i++) {
#pragma unroll
                for (int j = 0; j < 8; j++) {
                    unsigned long long bit = 1ull << (i * 8 + j);
                    if ((pend & bit) && !bufFull) {
                        float val = fmaf(-2.f, acc[i][j], xxr[j]);
                        if (val <= thrS[qb + i] && val < 1e30f) {
                            int pos = atomicAdd(s_count, 1);
                            if (pos < BUFCAP) {
                                bufv[pos] = val;
                                bufp[pos] = ((unsigned)(qb + i) << 18) | (unsigned)(t0 + nb + j);
                                pend &= ~bit;
                            } else {
                                bufFull = true;
                            }
                        } else {
                            pend &= ~bit;
                        }
                    }
                }
            }
            __syncthreads();
            int c = *s_count; if (c > BUFCAP) c = BUFCAP;

            // drain: each warp handles its own 16 queries
            for (int base = 0; base < c; base += 32) {
                int p = base + lane;
                float ev = 0.f; unsigned ep = 0u; bool mine = false;
                if (p < c) { ev = bufv[p]; ep = bufp[p]; mine = ((ep >> 22) == (unsigned)w); }
                unsigned m = __ballot_sync(0xffffffffu, mine);
                while (m) {
                    int src = __ffs(m) - 1; m &= m - 1;
                    float bval  = __shfl_sync(0xffffffffu, ev, src);
                    unsigned bp = __shfl_sync(0xffffffffu, ep, src);
                    int bq = (int)(bp >> 18);
                    int bn = (int)(bp & 0x3FFFFu);
                    if (bval > thrS[bq]) continue;
                    float tv = topv[bq * NK + lane];
                    int   ti = topi[bq * NK + lane];
                    // lexicographic argmax (worst entry): larger val, tie -> larger idx
                    float mv = tv; int mi = ti; int ml = lane;
#pragma unroll
                    for (int off = 16; off > 0; off >>= 1) {
                        float ov = __shfl_down_sync(0xffffffffu, mv, off);
                        int   oi = __shfl_down_sync(0xffffffffu, mi, off);
                        int   ol = __shfl_down_sync(0xffffffffu, ml, off);
                        if (ov > mv || (ov == mv && oi > mi)) { mv = ov; mi = oi; ml = ol; }
                    }
                    mv = __shfl_sync(0xffffffffu, mv, 0);
                    mi = __shfl_sync(0xffffffffu, mi, 0);
                    ml = __shfl_sync(0xffffffffu, ml, 0);
                    if (bval < mv || (bval == mv && bn < mi)) {
                        if (lane == ml) { topv[bq * NK + lane] = bval; topi[bq * NK + lane] = bn; }
                        __syncwarp();
                        float nv = (lane == ml) ? bval : tv;
#pragma unroll
                        for (int off = 16; off > 0; off >>= 1)
                            nv = fmaxf(nv, __shfl_down_sync(0xffffffffu, nv, off));
                        nv = __shfl_sync(0xffffffffu, nv, 0);
                        if (lane == 0) thrS[bq] = nv;
                        __syncwarp();
                    }
                }
            }
            __syncthreads();
            if (tid == 0) { *s_count = 0; *s_flag = 0; }
            __syncthreads();
            if (pend) *s_flag = 1;
            __syncthreads();
            if (!(*s_flag)) break;
        }
    }

    // write per-slice candidates
    for (int i = tid; i < MT * NK; i += THREADS) {
        int q = i >> 5, s = i & 31;
        int gq = mtile * MT + q;
        size_t o = ((size_t)gq * NSLICES + slice) * NK + s;
        g_cval[o] = topv[i];
        g_cidx[o] = topi[i];
    }
}

// ============================================================
// K2: merge per-slice candidates -> global top-32 per query
// ============================================================
#define NCAND (NSLICES * NK)  // 2368
__global__ void merge_kernel() {
    __shared__ float sv[NCAND];
    __shared__ int   si[NCAND];
    __shared__ float rvs[4]; __shared__ int ris[4]; __shared__ int rps[4];
    int b = blockIdx.x, tid = threadIdx.x;
    for (int i = tid; i < NCAND; i += 128) {
        sv[i] = g_cval[(size_t)b * NCAND + i];
        si[i] = g_cidx[(size_t)b * NCAND + i];
    }
    __syncthreads();
    for (int r = 0; r < NK; r++) {
        float bv = BIGV; int bi = 0x7FFFFFFF; int bp = 0;
        for (int i = tid; i < NCAND; i += 128) {
            float v = sv[i]; int ix = si[i];
            if (v < bv || (v == bv && ix < bi)) { bv = v; bi = ix; bp = i; }
        }
#pragma unroll
        for (int off = 16; off > 0; off >>= 1) {
            float ov = __shfl_down_sync(0xffffffffu, bv, off);
            int   oi = __shfl_down_sync(0xffffffffu, bi, off);
            int   op = __shfl_down_sync(0xffffffffu, bp, off);
            if (ov < bv || (ov == bv && oi < bi)) { bv = ov; bi = oi; bp = op; }
        }
        if ((tid & 31) == 0) { rvs[tid >> 5] = bv; ris[tid >> 5] = bi; rps[tid >> 5] = bp; }
        __syncthreads();
        if (tid == 0) {
            for (int wi = 1; wi < 4; wi++)
                if (rvs[wi] < rvs[0] || (rvs[wi] == rvs[0] && ris[wi] < ris[0])) {
                    rvs[0] = rvs[wi]; ris[0] = ris[wi]; rps[0] = rps[wi];
                }
            g_topk[b * NK + r] = ris[0];
            sv[rps[0]] = BIGV; si[rps[0]] = 0x7FFFFFFF;
        }
        __syncthreads();
    }
}

// ============================================================
// K3: gather neighbors + gated MLP head (one block per query)
// ============================================================
__global__ void mlp_kernel(const float* __restrict__ xq, const float* __restrict__ Xd,
                           const float* __restrict__ yv, const float* __restrict__ Wg,
                           const float* __restrict__ bg, const float* __restrict__ W1,
                           const float* __restrict__ b1, const float* __restrict__ Wl,
                           const float* __restrict__ bl, float* __restrict__ out) {
    __shared__ float nfs[NK * 65];
    __shared__ float Wgs[65 * NC];
    __shared__ float gs[NK * NC];
    __shared__ float xa[NF + NC];
    __shared__ float red[4];
    __shared__ int   idx[NK];
    int b = blockIdx.x, tid = threadIdx.x;

    if (tid < NK) idx[tid] = g_topk[b * NK + tid];
    for (int i = tid; i < 65 * NC; i += 128) Wgs[i] = Wg[i];
    __syncthreads();
    for (int i = tid; i < NK * NF; i += 128) {
        int k = i >> 6, f = i & 63;
        nfs[k * 65 + f] = Xd[(size_t)idx[k] * NF + f];
    }
    if (tid < NK) nfs[tid * 65 + 64] = yv[idx[tid]];
    __syncthreads();

    {   // gated = tanh(nf @ W_gate + b_gate): thread -> (k, c0..c0+3)
        int k = tid & 31, c0 = (tid >> 5) * 4;
        float a0 = bg[c0], a1 = bg[c0 + 1], a2 = bg[c0 + 2], a3 = bg[c0 + 3];
#pragma unroll 5
        for (int j = 0; j < 65; j++) {
            float v = nfs[k * 65 + j];
            a0 += v * Wgs[j * NC + c0];
            a1 += v * Wgs[j * NC + c0 + 1];
            a2 += v * Wgs[j * NC + c0 + 2];
            a3 += v * Wgs[j * NC + c0 + 3];
        }
        gs[k * NC + c0]     = tanhf(a0);
        gs[k * NC + c0 + 1] = tanhf(a1);
        gs[k * NC + c0 + 2] = tanhf(a2);
        gs[k * NC + c0 + 3] = tanhf(a3);
    }
    __syncthreads();
    if (tid < NF) {
        xa[tid] = xq[(size_t)b * NF + tid];
    } else if (tid < NF + NC) {
        int c = tid - NF;
        float s = 0.f;
#pragma unroll
        for (int k = 0; k < NK; k++) s += gs[k * NC + c];
        xa[tid] = s;
    }
    __syncthreads();

    float s = b1[tid];
#pragma unroll 8
    for (int i = 0; i < NF + NC; i++) s += xa[i] * W1[i * NH + tid];
    float oh = tanhf(s);
    float r = oh * Wl[tid];
#pragma unroll
    for (int off = 16; off > 0; off >>= 1) r += __shfl_down_sync(0xffffffffu, r, off);
    if ((tid & 31) == 0) red[tid >> 5] = r;
    __syncthreads();
    if (tid == 0) {
        float t = red[0] + red[1] + red[2] + red[3] + bl[0];
        out[b] = 1.f / (1.f + expf(-t));
    }
}

// ============================================================
extern "C" void kernel_launch(void* const* d_in, const int* in_sizes, int n_in,
                              void* d_out, int out_size) {
    (void)in_sizes; (void)n_in; (void)out_size;
    const float* xq = (const float*)d_in[0];
    const float* Xd = (const float*)d_in[1];
    const float* yv = (const float*)d_in[2];
    const float* Wg = (const float*)d_in[3];
    const float* bg = (const float*)d_in[4];
    const float* W1 = (const float*)d_in[5];
    const float* b1 = (const float*)d_in[6];
    const float* Wl = (const float*)d_in[7];
    const float* bl = (const float*)d_in[8];
    float* out = (float*)d_out;

    // dynamic smem for K1
    size_t smem_floats = (size_t)64 * QPAD * 2 + NT + (size_t)MT * NK + MT + BUFCAP; // float part
    size_t smem_ints   = (size_t)MT * NK + BUFCAP + 2;
    size_t smem_bytes  = (smem_floats + smem_ints) * 4;
    cudaFuncSetAttribute(knn_kernel, cudaFuncAttributeMaxDynamicSharedMemorySize, (int)smem_bytes);

    sqnorm_kernel<<<(ND + 63) / 64, 256>>>(Xd);
    knn_kernel<<<dim3(NQ / MT, NSLICES), THREADS, smem_bytes>>>(xq, Xd);
    merge_kernel<<<NQ, 128>>>();
    mlp_kernel<<<NQ, 128>>>(xq, Xd, yv, Wg, bg, W1, b1, Wl, bl, out);
}

// round 2
// speedup vs baseline: 5.2229x; 5.2229x over previous
#include <cuda_runtime.h>
#include <math.h>

// ---------------- problem constants ----------------
#define NQ 1024
#define ND 200000
#define NF 64
#define NK 32
#define NC 16
#define NH 128

// ---------------- GEMM tiling ----------------
#define MT 128
#define NT 128
#define THREADS 256
#define QP2 260          // dup-Q row pitch in floats (2*128 + 4 pad)
#define XP 132           // X row pitch in floats (128 + 4 pad)

#define SN 16384         // sample size for threshold
#define CAP 4096         // survivor capacity per query
#define NSL 18           // slices for main pass -> grid (8,18)=144 CTAs
#define SLICE_LEN 11136  // 18*11136 = 200448 >= 200000

#define BIGV 3.0e38f

// ---------------- static device scratch ----------------
__device__ float g_xx[ND];
__device__ float g_D[(size_t)NQ * SN];       // sample distances (67MB)
__device__ float g_tau[NQ];
__device__ int   g_cnt[NQ];
__device__ float g_sv[(size_t)NQ * CAP];
__device__ int   g_si[(size_t)NQ * CAP];
__device__ int   g_topk[NQ * NK];

// packed f32x2 fma: d = a*b + d
__device__ __forceinline__ void fma2(unsigned long long& d,
                                     const unsigned long long a,
                                     const unsigned long long b) {
    asm("fma.rn.f32x2 %0, %1, %2, %0;" : "+l"(d) : "l"(a), "l"(b));
}
__device__ __forceinline__ float2 unpack2(unsigned long long v) {
    float2 r;
    asm("mov.b64 {%0, %1}, %2;" : "=f"(r.x), "=f"(r.y) : "l"(v));
    return r;
}

// ============================================================
// K0: squared norms of X_data rows
// ============================================================
__global__ void sqnorm_kernel(const float* __restrict__ Xd) {
    int r = blockIdx.x * 64 + (threadIdx.x >> 2);
    int part = threadIdx.x & 3;
    if (r >= ND) return;
    const float4* row = (const float4*)(Xd + (size_t)r * NF);
    float s = 0.f;
#pragma unroll
    for (int l = 0; l < 4; l++) {
        float4 v = row[part + l * 4];
        s += v.x * v.x + v.y * v.y + v.z * v.z + v.w * v.w;
    }
    s += __shfl_xor_sync(0xffffffffu, s, 1);
    s += __shfl_xor_sync(0xffffffffu, s, 2);
    if (part == 0) g_xx[r] = s;
}

__global__ void zero_kernel() {
    int i = blockIdx.x * 256 + threadIdx.x;
    if (i < NQ) g_cnt[i] = 0;
}

// ============================================================
// GEMM core: score(q,n) = ||X_n||^2 - 2 x_q . X_n
// MODE 0: write scores of sample region to g_D
// MODE 1: filter vs g_tau, append survivors
// ============================================================
template <int MODE>
__global__ void __launch_bounds__(THREADS, 1)
gemm_kernel(const float* __restrict__ xq, const float* __restrict__ Xd) {
    extern __shared__ float smem[];
    float* Qs2 = smem;                 // 64 * QP2
    float* Xs  = Qs2 + 64 * QP2;       // 64 * XP
    float* Xxs = Xs + 64 * XP;         // NT

    const int tid = threadIdx.x;
    const int ty = tid >> 4;           // 0..15 -> 8 queries
    const int tx = tid & 15;           // 0..15 -> 8 points
    const int mtile = blockIdx.x;
    const int slice = blockIdx.y;

    // load Q tile, duplicated pairs: Qs2[f][2q] = Qs2[f][2q+1] = x[q][f]
    for (int i = tid; i < MT * NF; i += THREADS) {
        int q = i >> 6, f = i & 63;
        float v = xq[(size_t)(mtile * MT + q) * NF + f];
        Qs2[f * QP2 + 2 * q] = v;
        Qs2[f * QP2 + 2 * q + 1] = v;
    }

    float taur[8];
    if (MODE == 1) {
#pragma unroll
        for (int i = 0; i < 8; i++) {
            int q = (i < 4) ? (ty * 4 + i) : (64 + ty * 4 + (i - 4));
            taur[i] = g_tau[mtile * MT + q];
        }
    }

    int s_begin, s_end;
    if (MODE == 0) { s_begin = slice * 1024; s_end = s_begin + 1024; }
    else {
        s_begin = slice * SLICE_LEN;
        s_end = (s_begin + SLICE_LEN < ND) ? (s_begin + SLICE_LEN) : ND;
    }
    __syncthreads();

    for (int t0 = s_begin; t0 < s_end; t0 += NT) {
        // load X tile transposed (k-major), rotated scalar stores (~2-way conflicts)
        for (int i = tid; i < NT * 16; i += THREADS) {
            int n = i >> 4, c = i & 15;
            int gn = t0 + n;
            float4 v = (gn < s_end) ? ((const float4*)(Xd + (size_t)gn * NF))[c]
                                    : make_float4(0.f, 0.f, 0.f, 0.f);
            float arr[4] = {v.x, v.y, v.z, v.w};
#pragma unroll
            for (int s = 0; s < 4; s++) {
                int l = (s + c) & 3;
                Xs[(4 * c + l) * XP + n] = arr[l];
            }
        }
        if (tid < NT) Xxs[tid] = (t0 + tid < s_end) ? g_xx[t0 + tid] : BIGV;
        __syncthreads();

        unsigned long long accp[8][4];
#pragma unroll
        for (int i = 0; i < 8; i++)
#pragma unroll
            for (int j = 0; j < 4; j++) accp[i][j] = 0ull;

#pragma unroll 8
        for (int k = 0; k < NF; k++) {
            const float* qk = Qs2 + k * QP2 + 8 * ty;
            const float* xk = Xs + k * XP + 4 * tx;
            ulonglong2 qAB = *(const ulonglong2*)(qk);        // q: ty*4+0, +1
            ulonglong2 qCD = *(const ulonglong2*)(qk + 4);    // q: ty*4+2, +3
            ulonglong2 qEF = *(const ulonglong2*)(qk + 128);  // q: 64+ty*4+0, +1
            ulonglong2 qGH = *(const ulonglong2*)(qk + 132);  // q: 64+ty*4+2, +3
            ulonglong2 x01 = *(const ulonglong2*)(xk);        // n: tx*4 .. +3
            ulonglong2 x23 = *(const ulonglong2*)(xk + 64);   // n: 64+tx*4 .. +3

            fma2(accp[0][0], qAB.x, x01.x); fma2(accp[0][1], qAB.x, x01.y);
            fma2(accp[0][2], qAB.x, x23.x); fma2(accp[0][3], qAB.x, x23.y);
            fma2(accp[1][0], qAB.y, x01.x); fma2(accp[1][1], qAB.y, x01.y);
            fma2(accp[1][2], qAB.y, x23.x); fma2(accp[1][3], qAB.y, x23.y);
            fma2(accp[2][0], qCD.x, x01.x); fma2(accp[2][1], qCD.x, x01.y);
            fma2(accp[2][2], qCD.x, x23.x); fma2(accp[2][3], qCD.x, x23.y);
            fma2(accp[3][0], qCD.y, x01.x); fma2(accp[3][1], qCD.y, x01.y);
            fma2(accp[3][2], qCD.y, x23.x); fma2(accp[3][3], qCD.y, x23.y);
            fma2(accp[4][0], qEF.x, x01.x); fma2(accp[4][1], qEF.x, x01.y);
            fma2(accp[4][2], qEF.x, x23.x); fma2(accp[4][3], qEF.x, x23.y);
            fma2(accp[5][0], qEF.y, x01.x); fma2(accp[5][1], qEF.y, x01.y);
            fma2(accp[5][2], qEF.y, x23.x); fma2(accp[5][3], qEF.y, x23.y);
            fma2(accp[6][0], qGH.x, x01.x); fma2(accp[6][1], qGH.x, x01.y);
            fma2(accp[6][2], qGH.x, x23.x); fma2(accp[6][3], qGH.x, x23.y);
            fma2(accp[7][0], qGH.y, x01.x); fma2(accp[7][1], qGH.y, x01.y);
            fma2(accp[7][2], qGH.y, x23.x); fma2(accp[7][3], qGH.y, x23.y);
        }

        // epilogue
#pragma unroll
        for (int i = 0; i < 8; i++) {
            int gq = mtile * MT + ((i < 4) ? (ty * 4 + i) : (64 + ty * 4 + (i - 4)));
#pragma unroll
            for (int jp = 0; jp < 4; jp++) {
                int nl = (jp < 2) ? (tx * 4 + jp * 2) : (64 + tx * 4 + (jp - 2) * 2);
                float2 d = unpack2(accp[i][jp]);
                float v0 = fmaf(-2.f, d.x, Xxs[nl]);
                float v1 = fmaf(-2.f, d.y, Xxs[nl + 1]);
                if (MODE == 0) {
                    *(float2*)(g_D + (size_t)gq * SN + (t0 + nl)) = make_float2(v0, v1);
                } else {
                    if (v0 <= taur[i]) {
                        int pos = atomicAdd(&g_cnt[gq], 1);
                        if (pos < CAP) {
                            g_sv[(size_t)gq * CAP + pos] = v0;
                            g_si[(size_t)gq * CAP + pos] = t0 + nl;
                        }
                    }
                    if (v1 <= taur[i]) {
                        int pos = atomicAdd(&g_cnt[gq], 1);
                        if (pos < CAP) {
                            g_sv[(size_t)gq * CAP + pos] = v1;
                            g_si[(size_t)gq * CAP + pos] = t0 + nl + 1;
                        }
                    }
                }
            }
        }
        __syncthreads();
    }
}

// ============================================================
// tau: per-query 32nd-smallest of sample scores (+ tiny margin)
// ============================================================
__global__ void tau_kernel() {
    extern __shared__ float sD[];  // SN floats
    __shared__ float rv[16];
    __shared__ int rp[16];
    int b = blockIdx.x, tid = threadIdx.x;
    for (int i = tid; i < SN; i += 512) sD[i] = g_D[(size_t)b * SN + i];
    __syncthreads();
    for (int r = 0; r < NK; r++) {
        float bv = BIGV; int bp = 0x7FFFFFFF;
        for (int i = tid; i < SN; i += 512) {
            float v = sD[i];
            if (v < bv) { bv = v; bp = i; }
        }
#pragma unroll
        for (int off = 16; off > 0; off >>= 1) {
            float ov = __shfl_down_sync(0xffffffffu, bv, off);
            int op = __shfl_down_sync(0xffffffffu, bp, off);
            if (ov < bv || (ov == bv && op < bp)) { bv = ov; bp = op; }
        }
        if ((tid & 31) == 0) { rv[tid >> 5] = bv; rp[tid >> 5] = bp; }
        __syncthreads();
        if (tid == 0) {
            for (int wi = 1; wi < 16; wi++)
                if (rv[wi] < rv[0] || (rv[wi] == rv[0] && rp[wi] < rp[0])) {
                    rv[0] = rv[wi]; rp[0] = rp[wi];
                }
            sD[rp[0]] = BIGV;
            if (r == NK - 1) g_tau[b] = rv[0] + fabsf(rv[0]) * 1e-5f + 1e-5f;
        }
        __syncthreads();
    }
}

// ============================================================
// select: exact top-32 from survivors, (val, idx) tie-break
// ============================================================
__global__ void select_kernel() {
    __shared__ float sv[CAP];
    __shared__ int si[CAP];
    __shared__ float rv[8];
    __shared__ int ri[8], rp[8];
    int b = blockIdx.x, tid = threadIdx.x;
    int c = g_cnt[b]; if (c > CAP) c = CAP;
    for (int i = tid; i < CAP; i += 256) {
        sv[i] = (i < c) ? g_sv[(size_t)b * CAP + i] : BIGV;
        si[i] = (i < c) ? g_si[(size_t)b * CAP + i] : 0x7FFFFFFF;
    }
    __syncthreads();
    for (int r = 0; r < NK; r++) {
        float bv = BIGV; int bi = 0x7FFFFFFF; int bp = 0;
        for (int i = tid; i < CAP; i += 256) {
            float v = sv[i]; int ix = si[i];
            if (v < bv || (v == bv && ix < bi)) { bv = v; bi = ix; bp = i; }
        }
#pragma unroll
        for (int off = 16; off > 0; off >>= 1) {
            float ov = __shfl_down_sync(0xffffffffu, bv, off);
            int oi = __shfl_down_sync(0xffffffffu, bi, off);
            int op = __shfl_down_sync(0xffffffffu, bp, off);
            if (ov < bv || (ov == bv && oi < bi)) { bv = ov; bi = oi; bp = op; }
        }
        if ((tid & 31) == 0) { rv[tid >> 5] = bv; ri[tid >> 5] = bi; rp[tid >> 5] = bp; }
        __syncthreads();
        if (tid == 0) {
            for (int wi = 1; wi < 8; wi++)
                if (rv[wi] < rv[0] || (rv[wi] == rv[0] && ri[wi] < ri[0])) {
                    rv[0] = rv[wi]; ri[0] = ri[wi]; rp[0] = rp[wi];
                }
            g_topk[b * NK + r] = ri[0];
            sv[rp[0]] = BIGV; si[rp[0]] = 0x7FFFFFFF;
        }
        __syncthreads();
    }
}

// ============================================================
// mlp: gather neighbors + gated MLP head (one block per query)
// ============================================================
__global__ void mlp_kernel(const float* __restrict__ xq, const float* __restrict__ Xd,
                           const float* __restrict__ yv, const float* __restrict__ Wg,
                           const float* __restrict__ bg, const float* __restrict__ W1,
                           const float* __restrict__ b1, const float* __restrict__ Wl,
                           const float* __restrict__ bl, float* __restrict__ out) {
    __shared__ float nfs[NK * 65];
    __shared__ float Wgs[65 * NC];
    __shared__ float gs[NK * NC];
    __shared__ float xa[NF + NC];
    __shared__ float red[4];
    __shared__ int idx[NK];
    int b = blockIdx.x, tid = threadIdx.x;

    if (tid < NK) idx[tid] = g_topk[b * NK + tid];
    for (int i = tid; i < 65 * NC; i += 128) Wgs[i] = Wg[i];
    __syncthreads();
    for (int i = tid; i < NK * NF; i += 128) {
        int k = i >> 6, f = i & 63;
        nfs[k * 65 + f] = Xd[(size_t)idx[k] * NF + f];
    }
    if (tid < NK) nfs[tid * 65 + 64] = yv[idx[tid]];
    __syncthreads();

    {
        int k = tid & 31, c0 = (tid >> 5) * 4;
        float a0 = bg[c0], a1 = bg[c0 + 1], a2 = bg[c0 + 2], a3 = bg[c0 + 3];
#pragma unroll 5
        for (int j = 0; j < 65; j++) {
            float v = nfs[k * 65 + j];
            a0 += v * Wgs[j * NC + c0];
            a1 += v * Wgs[j * NC + c0 + 1];
            a2 += v * Wgs[j * NC + c0 + 2];
            a3 += v * Wgs[j * NC + c0 + 3];
        }
        gs[k * NC + c0] = tanhf(a0);
        gs[k * NC + c0 + 1] = tanhf(a1);
        gs[k * NC + c0 + 2] = tanhf(a2);
        gs[k * NC + c0 + 3] = tanhf(a3);
    }
    __syncthreads();
    if (tid < NF) {
        xa[tid] = xq[(size_t)b * NF + tid];
    } else if (tid < NF + NC) {
        int c = tid - NF;
        float s = 0.f;
#pragma unroll
        for (int k = 0; k < NK; k++) s += gs[k * NC + c];
        xa[tid] = s;
    }
    __syncthreads();

    float s = b1[tid];
#pragma unroll 8
    for (int i = 0; i < NF + NC; i++) s += xa[i] * W1[i * NH + tid];
    float oh = tanhf(s);
    float r = oh * Wl[tid];
#pragma unroll
    for (int off = 16; off > 0; off >>= 1) r += __shfl_down_sync(0xffffffffu, r, off);
    if ((tid & 31) == 0) red[tid >> 5] = r;
    __syncthreads();
    if (tid == 0) {
        float t = red[0] + red[1] + red[2] + red[3] + bl[0];
        out[b] = 1.f / (1.f + expf(-t));
    }
}

// ============================================================
extern "C" void kernel_launch(void* const* d_in, const int* in_sizes, int n_in,
                              void* d_out, int out_size) {
    (void)in_sizes; (void)n_in; (void)out_size;
    const float* xq = (const float*)d_in[0];
    const float* Xd = (const float*)d_in[1];
    const float* yv = (const float*)d_in[2];
    const float* Wg = (const float*)d_in[3];
    const float* bg = (const float*)d_in[4];
    const float* W1 = (const float*)d_in[5];
    const float* b1 = (const float*)d_in[6];
    const float* Wl = (const float*)d_in[7];
    const float* bl = (const float*)d_in[8];
    float* out = (float*)d_out;

    const size_t smem_g = (size_t)(64 * QP2 + 64 * XP + NT) * sizeof(float);
    cudaFuncSetAttribute(gemm_kernel<0>, cudaFuncAttributeMaxDynamicSharedMemorySize, (int)smem_g);
    cudaFuncSetAttribute(gemm_kernel<1>, cudaFuncAttributeMaxDynamicSharedMemorySize, (int)smem_g);
    cudaFuncSetAttribute(tau_kernel, cudaFuncAttributeMaxDynamicSharedMemorySize, SN * 4);

    zero_kernel<<<4, 256>>>();
    sqnorm_kernel<<<(ND + 63) / 64, 256>>>(Xd);
    gemm_kernel<0><<<dim3(NQ / MT, SN / 1024), THREADS, smem_g>>>(xq, Xd);
    tau_kernel<<<NQ, 512, SN * 4>>>();
    gemm_kernel<1><<<dim3(NQ / MT, NSL), THREADS, smem_g>>>(xq, Xd);
    select_kernel<<<NQ, 256>>>();
    mlp_kernel<<<NQ, 128>>>(xq, Xd, yv, Wg, bg, W1, b1, Wl, bl, out);
}

// round 4
// speedup vs baseline: 8.6677x; 1.6595x over previous
#include <cuda_runtime.h>
#include <cuda_bf16.h>
#include <math.h>
#include <stdint.h>

// ---------------- problem constants ----------------
#define NQ 1024
#define ND 200000
#define NF 64
#define NK 32
#define NC 16
#define NH 128

#define MT 128           // queries per CTA
#define NT 128           // points per tile
#define NSL 19           // main-pass slices -> grid (8,19)=152 CTAs
#define MAIN_TILES 83    // 19*83*128 = 201856 >= 200000
#define NDPAD 201856
#define SN 16384         // sample size
#define SAMPLE_SLICES 8
#define SAMPLE_TILES 16
#define CAP 4096
#define MARGIN 2.0f      // 2E safety margin on bf16 approx scores
#define BIGV 3.0e38f

// ---------------- static device scratch ----------------
__device__ float          g_xxp[NDPAD];
__device__ __nv_bfloat16  g_Xb[(size_t)NDPAD * NF];
__device__ __nv_bfloat16  g_Qb[(size_t)NQ * NF];
__device__ float          g_D[(size_t)NQ * SN];
__device__ float          g_tau[NQ];
__device__ int            g_cnt[NQ];
__device__ float          g_sv[(size_t)NQ * CAP];
__device__ int            g_si[(size_t)NQ * CAP];
__device__ int            g_topk[NQ * NK];

// ---------------- helpers ----------------
__device__ __forceinline__ uint32_t smem_u32(const void* p) {
    uint32_t a;
    asm("{ .reg .u64 t; cvta.to.shared.u64 t, %1; cvt.u32.u64 %0, t; }" : "=r"(a) : "l"(p));
    return a;
}
#define SWZ128(o) ((o) ^ (((o) >> 3) & 0x70))

__device__ __forceinline__ void cpa16(uint32_t d, const void* s) {
    asm volatile("cp.async.cg.shared.global [%0], [%1], 16;" :: "r"(d), "l"(s) : "memory");
}
#define CPA_COMMIT() asm volatile("cp.async.commit_group;" ::: "memory")

__device__ __forceinline__ void ldsm4(uint32_t* r, uint32_t a) {
    asm volatile("ldmatrix.sync.aligned.m8n8.x4.shared.b16 {%0,%1,%2,%3}, [%4];"
                 : "=r"(r[0]), "=r"(r[1]), "=r"(r[2]), "=r"(r[3]) : "r"(a));
}
__device__ __forceinline__ void mma16816(float* d, const uint32_t* a, const uint32_t* b) {
    asm volatile(
        "mma.sync.aligned.m16n8k16.row.col.f32.bf16.bf16.f32 "
        "{%0,%1,%2,%3}, {%4,%5,%6,%7}, {%8,%9}, {%0,%1,%2,%3};"
        : "+f"(d[0]), "+f"(d[1]), "+f"(d[2]), "+f"(d[3])
        : "r"(a[0]), "r"(a[1]), "r"(a[2]), "r"(a[3]), "r"(b[0]), "r"(b[1]));
}

// ---------------- smem layout (bytes) ----------------
#define SMQ    0
#define SMX0   16384
#define SMX1   32768
#define SMXX0  49152
#define SMXX1  49664
#define SMTAU  50176
#define SM_TOTAL 50688

// ============================================================
// prep_x: exact fp32 norms + bf16 conversion + padding
// ============================================================
__global__ void prep_x_kernel(const float* __restrict__ Xd) {
    int r = blockIdx.x * 64 + (threadIdx.x >> 2);
    int part = threadIdx.x & 3;
    if (r >= NDPAD) return;
    uint4* dst = (uint4*)(g_Xb + (size_t)r * NF) + part * 2;
    if (r < ND) {
        const float4* row = (const float4*)(Xd + (size_t)r * NF) + part * 4;
        float4 v[4];
        float s = 0.f;
#pragma unroll
        for (int l = 0; l < 4; l++) {
            v[l] = row[l];
            s += v[l].x * v[l].x + v[l].y * v[l].y + v[l].z * v[l].z + v[l].w * v[l].w;
        }
        s += __shfl_xor_sync(0xffffffffu, s, 1);
        s += __shfl_xor_sync(0xffffffffu, s, 2);
        if (part == 0) g_xxp[r] = s;
        unsigned u[8];
#pragma unroll
        for (int l = 0; l < 4; l++) {
            __nv_bfloat162 h0 = __floats2bfloat162_rn(v[l].x, v[l].y);
            __nv_bfloat162 h1 = __floats2bfloat162_rn(v[l].z, v[l].w);
            u[l * 2]     = *(unsigned*)&h0;
            u[l * 2 + 1] = *(unsigned*)&h1;
        }
        dst[0] = make_uint4(u[0], u[1], u[2], u[3]);
        dst[1] = make_uint4(u[4], u[5], u[6], u[7]);
    } else {
        if (part == 0) g_xxp[r] = BIGV;
        uint4 z = make_uint4(0, 0, 0, 0);
        dst[0] = z; dst[1] = z;
    }
}

// prep_q: g_Qb = bf16(-2 * x)
__global__ void prep_q_kernel(const float* __restrict__ xq) {
    int i = blockIdx.x * 256 + threadIdx.x;
    float2 v = ((const float2*)xq)[i];
    __nv_bfloat162 h = __floats2bfloat162_rn(-2.f * v.x, -2.f * v.y);
    ((__nv_bfloat162*)g_Qb)[i] = h;
}

__global__ void zero_kernel() {
    int i = blockIdx.x * 256 + threadIdx.x;
    if (i < NQ) g_cnt[i] = 0;
}

// ============================================================
// MMA kernel (mma.sync bf16): score(q,n) = ||X_n||^2 - 2 x.X_n (approx)
// MODE 0: write approx scores of sample region to g_D
// MODE 1: filter vs g_tau, append survivor indices
// ============================================================
template <int MODE, int NTILES>
__global__ void __launch_bounds__(256, 1)
mma_kernel() {
    extern __shared__ char smem[];
    const uint32_t sb = smem_u32(smem);
    const int tid = threadIdx.x;
    const int lane = tid & 31;
    const int wid = tid >> 5;
    const int mtile = blockIdx.x;
    const int base = blockIdx.y * NTILES * NT;

    // load Q tile into swizzled smem (128 rows x 128B)
    {
        const uint4* qsrc = (const uint4*)(g_Qb + (size_t)mtile * MT * NF);
#pragma unroll
        for (int c = 0; c < 4; c++) {
            int ch = tid + c * 256;
            int row = ch >> 3, col = ch & 7;
            *(uint4*)(smem + SMQ + SWZ128(row * 128 + col * 16)) = qsrc[ch];
        }
    }
    if (MODE == 1 && tid < MT) ((float*)(smem + SMTAU))[tid] = g_tau[mtile * MT + tid];

    // async-load X tile 0
    {
        const uint4* xs = (const uint4*)(g_Xb + (size_t)base * NF);
#pragma unroll
        for (int c = 0; c < 4; c++) {
            int ch = tid + c * 256;
            int row = ch >> 3, col = ch & 7;
            cpa16(sb + SMX0 + SWZ128(row * 128 + col * 16), xs + ch);
        }
        if (tid < 32) cpa16(sb + SMXX0 + tid * 16, g_xxp + base + tid * 4);
        CPA_COMMIT();
    }
    __syncthreads();

    const int wr = wid >> 2;          // 0..1 : m-half
    const int wc = wid & 3;           // 0..3 : n-quarter
    const int m0 = wr * 64;
    const int nb = wc * 32;
    const int tq = lane >> 2;         // row within 8
    const int tn2 = (lane & 3) * 2;   // col pair within 8

    float tr[8];
    if (MODE == 1) {
        const float* tsm = (const float*)(smem + SMTAU);
#pragma unroll
        for (int mf = 0; mf < 4; mf++) {
            tr[mf * 2]     = tsm[m0 + mf * 16 + tq];
            tr[mf * 2 + 1] = tsm[m0 + mf * 16 + 8 + tq];
        }
    }

    // ldmatrix lane addressing
    const int a_row = lane & 15, a_kh = lane >> 4;
    const int b_row = (lane & 7) | ((lane >> 4) << 3), b_kh = (lane >> 3) & 1;

    for (int t = 0; t < NTILES; t++) {
        const int t0 = base + t * NT;
        const uint32_t xb  = (t & 1) ? SMX1 : SMX0;
        const uint32_t xxb = (t & 1) ? SMXX1 : SMXX0;

        // prefetch t+1 into the other buffer
        if (t + 1 < NTILES) {
            const uint4* xs = (const uint4*)(g_Xb + (size_t)(t0 + NT) * NF);
            uint32_t dxb  = (t & 1) ? SMX0 : SMX1;
            uint32_t dxxb = (t & 1) ? SMXX0 : SMXX1;
#pragma unroll
            for (int c = 0; c < 4; c++) {
                int ch = tid + c * 256;
                int row = ch >> 3, col = ch & 7;
                cpa16(sb + dxb + SWZ128(row * 128 + col * 16), xs + ch);
            }
            if (tid < 32) cpa16(sb + dxxb + tid * 16, g_xxp + t0 + NT + tid * 4);
            CPA_COMMIT();
            asm volatile("cp.async.wait_group 1;" ::: "memory");
        } else {
            asm volatile("cp.async.wait_group 0;" ::: "memory");
        }
        __syncthreads();

        float d[4][4][4];
#pragma unroll
        for (int i = 0; i < 4; i++)
#pragma unroll
            for (int j = 0; j < 4; j++)
#pragma unroll
                for (int k = 0; k < 4; k++) d[i][j][k] = 0.f;

#pragma unroll
        for (int ks = 0; ks < 4; ks++) {
            uint32_t a[4][4], b[4][2];
#pragma unroll
            for (int mf = 0; mf < 4; mf++) {
                uint32_t addr = sb + SMQ +
                    SWZ128((m0 + mf * 16 + a_row) * 128 + ks * 32 + a_kh * 16);
                ldsm4(a[mf], addr);
            }
#pragma unroll
            for (int h = 0; h < 2; h++) {
                uint32_t r[4];
                uint32_t addr = sb + xb +
                    SWZ128((nb + h * 16 + b_row) * 128 + ks * 32 + b_kh * 16);
                ldsm4(r, addr);
                b[h * 2][0] = r[0]; b[h * 2][1] = r[1];
                b[h * 2 + 1][0] = r[2]; b[h * 2 + 1][1] = r[3];
            }
#pragma unroll
            for (int mf = 0; mf < 4; mf++)
#pragma unroll
                for (int nf = 0; nf < 4; nf++) mma16816(d[mf][nf], a[mf], b[nf]);
        }

        // epilogue
        const float* xxs = (const float*)(smem + xxb);
        float2 xv[4];
#pragma unroll
        for (int nf = 0; nf < 4; nf++) xv[nf] = *(const float2*)(xxs + nb + nf * 8 + tn2);

#pragma unroll
        for (int mf = 0; mf < 4; mf++) {
#pragma unroll
            for (int h = 0; h < 2; h++) {
                const int gq = mtile * MT + m0 + mf * 16 + h * 8 + tq;
                if (MODE == 0) {
                    float* dst = g_D + (size_t)gq * SN + (t0 + nb + tn2);
#pragma unroll
                    for (int nf = 0; nf < 4; nf++) {
                        float v0 = d[mf][nf][h * 2] + xv[nf].x;
                        float v1 = d[mf][nf][h * 2 + 1] + xv[nf].y;
                        *(float2*)(dst + nf * 8) = make_float2(v0, v1);
                    }
                } else {
                    const float tau = tr[mf * 2 + h];
#pragma unroll
                    for (int nf = 0; nf < 4; nf++) {
                        float v0 = d[mf][nf][h * 2] + xv[nf].x;
                        float v1 = d[mf][nf][h * 2 + 1] + xv[nf].y;
                        if (v0 <= tau) {
                            int pos = atomicAdd(&g_cnt[gq], 1);
                            if (pos < CAP) g_si[(size_t)gq * CAP + pos] = t0 + nb + nf * 8 + tn2;
                        }
                        if (v1 <= tau) {
                            int pos = atomicAdd(&g_cnt[gq], 1);
                            if (pos < CAP) g_si[(size_t)gq * CAP + pos] = t0 + nb + nf * 8 + tn2 + 1;
                        }
                    }
                }
            }
        }
        __syncthreads();
    }
}

// ============================================================
// tau: radix-select 32nd smallest approx sample score + margin
// ============================================================
__global__ void tau_kernel() {
    extern __shared__ unsigned sU[];
    __shared__ unsigned hist[256];
    __shared__ unsigned s_prefix;
    __shared__ int s_rank;
    const int b = blockIdx.x, tid = threadIdx.x;

    for (int i = tid; i < SN; i += 256) {
        unsigned u = __float_as_uint(g_D[(size_t)b * SN + i]);
        sU[i] = (u & 0x80000000u) ? ~u : (u | 0x80000000u);
    }
    if (tid == 0) { s_prefix = 0u; s_rank = NK; }
    __syncthreads();

#pragma unroll
    for (int lev = 0; lev < 4; lev++) {
        const int sh = 24 - 8 * lev;
        const unsigned mask = (lev == 0) ? 0u : (0xFFFFFFFFu << (sh + 8));
        hist[tid] = 0;
        __syncthreads();
        const unsigned pfx = s_prefix;
        for (int i = tid; i < SN; i += 256) {
            unsigned u = sU[i];
            if ((u & mask) == pfx) atomicAdd(&hist[(u >> sh) & 255u], 1u);
        }
        __syncthreads();
        if (tid == 0) {
            int r = s_rank;
            unsigned cum = 0;
            for (int k = 0; k < 256; k++) {
                unsigned h = hist[k];
                if (cum + h >= (unsigned)r) { s_rank = r - (int)cum; s_prefix = pfx | ((unsigned)k << sh); break; }
                cum += h;
            }
        }
        __syncthreads();
    }
    if (tid == 0) {
        unsigned u = s_prefix;
        unsigned bb = (u & 0x80000000u) ? (u ^ 0x80000000u) : ~u;
        g_tau[b] = __uint_as_float(bb) + MARGIN;
    }
}

// ============================================================
// rescore: exact fp32 score per survivor (warp per survivor)
// ============================================================
__global__ void rescore_kernel(const float* __restrict__ xq, const float* __restrict__ Xd) {
    __shared__ float xs[NF];
    const int b = blockIdx.x, tid = threadIdx.x;
    if (tid < NF) xs[tid] = xq[(size_t)b * NF + tid];
    __syncthreads();
    int c = g_cnt[b]; if (c > CAP) c = CAP;
    const int w = tid >> 5, lane = tid & 31;
    float2 xv = *(const float2*)(xs + 2 * lane);
    for (int s = w; s < c; s += 8) {
        int n = g_si[(size_t)b * CAP + s];
        float2 Xv = *(const float2*)(Xd + (size_t)n * NF + 2 * lane);
        float p = xv.x * Xv.x + xv.y * Xv.y;
#pragma unroll
        for (int off = 16; off > 0; off >>= 1) p += __shfl_xor_sync(0xffffffffu, p, off);
        if (lane == 0) g_sv[(size_t)b * CAP + s] = g_xxp[n] - 2.f * p;
    }
}

// ============================================================
// select: exact top-32 from survivors, (val, idx) tie-break
// ============================================================
__global__ void select_kernel() {
    __shared__ float sv[CAP];
    __shared__ int si[CAP];
    __shared__ float rv[8];
    __shared__ int ri[8], rp[8];
    const int b = blockIdx.x, tid = threadIdx.x;
    int c = g_cnt[b]; if (c > CAP) c = CAP;
    const int cpad = (c + 255) & ~255;
    for (int i = tid; i < cpad; i += 256) {
        sv[i] = (i < c) ? g_sv[(size_t)b * CAP + i] : BIGV;
        si[i] = (i < c) ? g_si[(size_t)b * CAP + i] : 0x7FFFFFFF;
    }
    __syncthreads();
    for (int r = 0; r < NK; r++) {
        float bv = BIGV; int bi = 0x7FFFFFFF; int bp = 0;
        for (int i = tid; i < cpad; i += 256) {
            float v = sv[i]; int ix = si[i];
            if (v < bv || (v == bv && ix < bi)) { bv = v; bi = ix; bp = i; }
        }
#pragma unroll
        for (int off = 16; off > 0; off >>= 1) {
            float ov = __shfl_down_sync(0xffffffffu, bv, off);
            int oi = __shfl_down_sync(0xffffffffu, bi, off);
            int op = __shfl_down_sync(0xffffffffu, bp, off);
            if (ov < bv || (ov == bv && oi < bi)) { bv = ov; bi = oi; bp = op; }
        }
        if ((tid & 31) == 0) { rv[tid >> 5] = bv; ri[tid >> 5] = bi; rp[tid >> 5] = bp; }
        __syncthreads();
        if (tid == 0) {
            for (int wi = 1; wi < 8; wi++)
                if (rv[wi] < rv[0] || (rv[wi] == rv[0] && ri[wi] < ri[0])) {
                    rv[0] = rv[wi]; ri[0] = ri[wi]; rp[0] = rp[wi];
                }
            g_topk[b * NK + r] = ri[0];
            sv[rp[0]] = BIGV; si[rp[0]] = 0x7FFFFFFF;
        }
        __syncthreads();
    }
}

// ============================================================
// mlp: gather neighbors + gated MLP head (one block per query)
// ============================================================
__global__ void mlp_kernel(const float* __restrict__ xq, const float* __restrict__ Xd,
                           const float* __restrict__ yv, const float* __restrict__ Wg,
                           const float* __restrict__ bg, const float* __restrict__ W1,
                           const float* __restrict__ b1, const float* __restrict__ Wl,
                           const float* __restrict__ bl, float* __restrict__ out) {
    __shared__ float nfs[NK * 65];
    __shared__ float Wgs[65 * NC];
    __shared__ float gs[NK * NC];
    __shared__ float xa[NF + NC];
    __shared__ float red[4];
    __shared__ int idx[NK];
    const int b = blockIdx.x, tid = threadIdx.x;

    if (tid < NK) idx[tid] = g_topk[b * NK + tid];
    for (int i = tid; i < 65 * NC; i += 128) Wgs[i] = Wg[i];
    __syncthreads();
    for (int i = tid; i < NK * NF; i += 128) {
        int k = i >> 6, f = i & 63;
        nfs[k * 65 + f] = Xd[(size_t)idx[k] * NF + f];
    }
    if (tid < NK) nfs[tid * 65 + 64] = yv[idx[tid]];
    __syncthreads();

    {
        int k = tid & 31, c0 = (tid >> 5) * 4;
        float a0 = bg[c0], a1 = bg[c0 + 1], a2 = bg[c0 + 2], a3 = bg[c0 + 3];
#pragma unroll 5
        for (int j = 0; j < 65; j++) {
            float v = nfs[k * 65 + j];
            a0 += v * Wgs[j * NC + c0];
            a1 += v * Wgs[j * NC + c0 + 1];
            a2 += v * Wgs[j * NC + c0 + 2];
            a3 += v * Wgs[j * NC + c0 + 3];
        }
        gs[k * NC + c0] = tanhf(a0);
        gs[k * NC + c0 + 1] = tanhf(a1);
        gs[k * NC + c0 + 2] = tanhf(a2);
        gs[k * NC + c0 + 3] = tanhf(a3);
    }
    __syncthreads();
    if (tid < NF) {
        xa[tid] = xq[(size_t)b * NF + tid];
    } else if (tid < NF + NC) {
        int c = tid - NF;
        float s = 0.f;
#pragma unroll
        for (int k = 0; k < NK; k++) s += gs[k * NC + c];
        xa[tid] = s;
    }
    __syncthreads();

    float s = b1[tid];
#pragma unroll 8
    for (int i = 0; i < NF + NC; i++) s += xa[i] * W1[i * NH + tid];
    float oh = tanhf(s);
    float r = oh * Wl[tid];
#pragma unroll
    for (int off = 16; off > 0; off >>= 1) r += __shfl_down_sync(0xffffffffu, r, off);
    if ((tid & 31) == 0) red[tid >> 5] = r;
    __syncthreads();
    if (tid == 0) {
        float t = red[0] + red[1] + red[2] + red[3] + bl[0];
        out[b] = 1.f / (1.f + expf(-t));
    }
}

// ============================================================
extern "C" void kernel_launch(void* const* d_in, const int* in_sizes, int n_in,
                              void* d_out, int out_size) {
    (void)in_sizes; (void)n_in; (void)out_size;
    const float* xq = (const float*)d_in[0];
    const float* Xd = (const float*)d_in[1];
    const float* yv = (const float*)d_in[2];
    const float* Wg = (const float*)d_in[3];
    const float* bg = (const float*)d_in[4];
    const float* W1 = (const float*)d_in[5];
    const float* b1 = (const float*)d_in[6];
    const float* Wl = (const float*)d_in[7];
    const float* bl = (const float*)d_in[8];
    float* out = (float*)d_out;

    cudaFuncSetAttribute(mma_kernel<0, SAMPLE_TILES>, cudaFuncAttributeMaxDynamicSharedMemorySize, SM_TOTAL);
    cudaFuncSetAttribute(mma_kernel<1, MAIN_TILES>, cudaFuncAttributeMaxDynamicSharedMemorySize, SM_TOTAL);
    cudaFuncSetAttribute(tau_kernel, cudaFuncAttributeMaxDynamicSharedMemorySize, SN * 4);

    prep_x_kernel<<<NDPAD / 64, 256>>>(Xd);
    prep_q_kernel<<<128, 256>>>(xq);
    zero_kernel<<<4, 256>>>();
    mma_kernel<0, SAMPLE_TILES><<<dim3(NQ / MT, SAMPLE_SLICES), 256, SM_TOTAL>>>();
    tau_kernel<<<NQ, 256, SN * 4>>>();
    mma_kernel<1, MAIN_TILES><<<dim3(NQ / MT, NSL), 256, SM_TOTAL>>>();
    rescore_kernel<<<NQ, 256>>>(xq, Xd);
    select_kernel<<<NQ, 256>>>();
    mlp_kernel<<<NQ, 128>>>(xq, Xd, yv, Wg, bg, W1, b1, Wl, bl, out);
}

// round 5
// speedup vs baseline: 12.0236x; 1.3872x over previous
#include <cuda_runtime.h>
#include <cuda_bf16.h>
#include <math.h>
#include <stdint.h>

// ---------------- problem constants ----------------
#define NQ 1024
#define ND 200000
#define NF 64
#define NK 32
#define NC 16
#define NH 128

#define MT 128           // queries per CTA
#define NT 128           // points per tile
#define NSL 38           // main-pass slices -> grid (8,38)=304 CTAs
#define MAIN_TILES 42    // 38*42*128 = 204288 >= 200000
#define NDPAD 204288
#define SN 16384         // sample size
#define SAMPLE_SLICES 16
#define SAMPLE_TILES 8
#define CAP 4096
#define MARGIN 4.0f      // 2*E_mma + E_bf16store safety margin
#define BIGV 3.0e38f

// ---------------- static device scratch ----------------
__device__ float          g_xxp[NDPAD];
__device__ __nv_bfloat16  g_Xb[(size_t)NDPAD * NF];
__device__ __nv_bfloat16  g_Qb[(size_t)NQ * NF];
__device__ unsigned short g_Du[(size_t)NQ * SN];   // bf16 sample scores
__device__ float          g_tau[NQ];
__device__ int            g_cnt[NQ];
__device__ float          g_sv[(size_t)NQ * CAP];
__device__ int            g_si[(size_t)NQ * CAP];
__device__ int            g_topk[NQ * NK];

// ---------------- helpers ----------------
__device__ __forceinline__ uint32_t smem_u32(const void* p) {
    uint32_t a;
    asm("{ .reg .u64 t; cvta.to.shared.u64 t, %1; cvt.u32.u64 %0, t; }" : "=r"(a) : "l"(p));
    return a;
}
#define SWZ128(o) ((o) ^ (((o) >> 3) & 0x70))

__device__ __forceinline__ void cpa16(uint32_t d, const void* s) {
    asm volatile("cp.async.cg.shared.global [%0], [%1], 16;" :: "r"(d), "l"(s) : "memory");
}
#define CPA_COMMIT() asm volatile("cp.async.commit_group;" ::: "memory")

__device__ __forceinline__ void ldsm4(uint32_t* r, uint32_t a) {
    asm volatile("ldmatrix.sync.aligned.m8n8.x4.shared.b16 {%0,%1,%2,%3}, [%4];"
                 : "=r"(r[0]), "=r"(r[1]), "=r"(r[2]), "=r"(r[3]) : "r"(a));
}
__device__ __forceinline__ void mma16816(float* d, const uint32_t* a, const uint32_t* b) {
    asm volatile(
        "mma.sync.aligned.m16n8k16.row.col.f32.bf16.bf16.f32 "
        "{%0,%1,%2,%3}, {%4,%5,%6,%7}, {%8,%9}, {%0,%1,%2,%3};"
        : "+f"(d[0]), "+f"(d[1]), "+f"(d[2]), "+f"(d[3])
        : "r"(a[0]), "r"(a[1]), "r"(a[2]), "r"(a[3]), "r"(b[0]), "r"(b[1]));
}
__device__ __forceinline__ unsigned short f2bf(float v) {
    __nv_bfloat16 h = __float2bfloat16(v);
    return *(unsigned short*)&h;
}

// ---------------- smem layout (bytes) ----------------
#define SMQ    0
#define SMX0   16384
#define SMX1   32768
#define SMXX0  49152
#define SMXX1  49664
#define SMTAU  50176
#define SM_TOTAL 50688

// ============================================================
// prep_x: exact fp32 norms + bf16 conversion + padding
// ============================================================
__global__ void prep_x_kernel(const float* __restrict__ Xd) {
    int r = blockIdx.x * 64 + (threadIdx.x >> 2);
    int part = threadIdx.x & 3;
    if (r >= NDPAD) return;
    uint4* dst = (uint4*)(g_Xb + (size_t)r * NF) + part * 2;
    if (r < ND) {
        const float4* row = (const float4*)(Xd + (size_t)r * NF) + part * 4;
        float4 v[4];
        float s = 0.f;
#pragma unroll
        for (int l = 0; l < 4; l++) {
            v[l] = row[l];
            s += v[l].x * v[l].x + v[l].y * v[l].y + v[l].z * v[l].z + v[l].w * v[l].w;
        }
        s += __shfl_xor_sync(0xffffffffu, s, 1);
        s += __shfl_xor_sync(0xffffffffu, s, 2);
        if (part == 0) g_xxp[r] = s;
        unsigned u[8];
#pragma unroll
        for (int l = 0; l < 4; l++) {
            __nv_bfloat162 h0 = __floats2bfloat162_rn(v[l].x, v[l].y);
            __nv_bfloat162 h1 = __floats2bfloat162_rn(v[l].z, v[l].w);
            u[l * 2]     = *(unsigned*)&h0;
            u[l * 2 + 1] = *(unsigned*)&h1;
        }
        dst[0] = make_uint4(u[0], u[1], u[2], u[3]);
        dst[1] = make_uint4(u[4], u[5], u[6], u[7]);
    } else {
        if (part == 0) g_xxp[r] = BIGV;
        uint4 z = make_uint4(0, 0, 0, 0);
        dst[0] = z; dst[1] = z;
    }
}

// prep_q: g_Qb = bf16(-2 * x)
__global__ void prep_q_kernel(const float* __restrict__ xq) {
    int i = blockIdx.x * 256 + threadIdx.x;
    float2 v = ((const float2*)xq)[i];
    __nv_bfloat162 h = __floats2bfloat162_rn(-2.f * v.x, -2.f * v.y);
    ((__nv_bfloat162*)g_Qb)[i] = h;
}

__global__ void zero_kernel() {
    int i = blockIdx.x * 256 + threadIdx.x;
    if (i < NQ) g_cnt[i] = 0;
}

// ============================================================
// MMA kernel (mma.sync bf16): score(q,n) = ||X_n||^2 - 2 x.X_n (approx)
// MODE 0: write bf16 approx scores of sample region to g_Du
// MODE 1: filter vs g_tau, append survivor indices
// ============================================================
template <int MODE, int NTILES>
__global__ void __launch_bounds__(256, 2)
mma_kernel() {
    extern __shared__ char smem[];
    const uint32_t sb = smem_u32(smem);
    const int tid = threadIdx.x;
    const int lane = tid & 31;
    const int wid = tid >> 5;
    const int mtile = blockIdx.x;
    const int base = blockIdx.y * NTILES * NT;

    // load Q tile into swizzled smem (128 rows x 128B)
    {
        const uint4* qsrc = (const uint4*)(g_Qb + (size_t)mtile * MT * NF);
#pragma unroll
        for (int c = 0; c < 4; c++) {
            int ch = tid + c * 256;
            int row = ch >> 3, col = ch & 7;
            *(uint4*)(smem + SMQ + SWZ128(row * 128 + col * 16)) = qsrc[ch];
        }
    }
    if (MODE == 1 && tid < MT) ((float*)(smem + SMTAU))[tid] = g_tau[mtile * MT + tid];

    // async-load X tile 0
    {
        const uint4* xs = (const uint4*)(g_Xb + (size_t)base * NF);
#pragma unroll
        for (int c = 0; c < 4; c++) {
            int ch = tid + c * 256;
            int row = ch >> 3, col = ch & 7;
            cpa16(sb + SMX0 + SWZ128(row * 128 + col * 16), xs + ch);
        }
        if (tid < 32) cpa16(sb + SMXX0 + tid * 16, g_xxp + base + tid * 4);
        CPA_COMMIT();
    }
    __syncthreads();

    const int wr = wid >> 2;          // 0..1 : m-half
    const int wc = wid & 3;           // 0..3 : n-quarter
    const int m0 = wr * 64;
    const int nb = wc * 32;
    const int tq = lane >> 2;         // row within 8
    const int tn2 = (lane & 3) * 2;   // col pair within 8

    // ldmatrix lane addressing
    const int a_row = lane & 15, a_kh = lane >> 4;
    const int b_row = (lane & 7) | ((lane >> 4) << 3), b_kh = (lane >> 3) & 1;

    for (int t = 0; t < NTILES; t++) {
        const int t0 = base + t * NT;
        const uint32_t xb  = (t & 1) ? SMX1 : SMX0;
        const uint32_t xxb = (t & 1) ? SMXX1 : SMXX0;

        // prefetch t+1 into the other buffer
        if (t + 1 < NTILES) {
            const uint4* xs = (const uint4*)(g_Xb + (size_t)(t0 + NT) * NF);
            uint32_t dxb  = (t & 1) ? SMX0 : SMX1;
            uint32_t dxxb = (t & 1) ? SMXX0 : SMXX1;
#pragma unroll
            for (int c = 0; c < 4; c++) {
                int ch = tid + c * 256;
                int row = ch >> 3, col = ch & 7;
                cpa16(sb + dxb + SWZ128(row * 128 + col * 16), xs + ch);
            }
            if (tid < 32) cpa16(sb + dxxb + tid * 16, g_xxp + t0 + NT + tid * 4);
            CPA_COMMIT();
            asm volatile("cp.async.wait_group 1;" ::: "memory");
        } else {
            asm volatile("cp.async.wait_group 0;" ::: "memory");
        }
        __syncthreads();

        float d[4][4][4];
#pragma unroll
        for (int i = 0; i < 4; i++)
#pragma unroll
            for (int j = 0; j < 4; j++)
#pragma unroll
                for (int k = 0; k < 4; k++) d[i][j][k] = 0.f;

#pragma unroll
        for (int ks = 0; ks < 4; ks++) {
            uint32_t a[4][4], b[4][2];
#pragma unroll
            for (int mf = 0; mf < 4; mf++) {
                uint32_t addr = sb + SMQ +
                    SWZ128((m0 + mf * 16 + a_row) * 128 + ks * 32 + a_kh * 16);
                ldsm4(a[mf], addr);
            }
#pragma unroll
            for (int h = 0; h < 2; h++) {
                uint32_t r[4];
                uint32_t addr = sb + xb +
                    SWZ128((nb + h * 16 + b_row) * 128 + ks * 32 + b_kh * 16);
                ldsm4(r, addr);
                b[h * 2][0] = r[0]; b[h * 2][1] = r[1];
                b[h * 2 + 1][0] = r[2]; b[h * 2 + 1][1] = r[3];
            }
#pragma unroll
            for (int mf = 0; mf < 4; mf++)
#pragma unroll
                for (int nf = 0; nf < 4; nf++) mma16816(d[mf][nf], a[mf], b[nf]);
        }

        // epilogue
        const float* xxs = (const float*)(smem + xxb);
        float2 xv[4];
#pragma unroll
        for (int nf = 0; nf < 4; nf++) xv[nf] = *(const float2*)(xxs + nb + nf * 8 + tn2);

        const float* tsm = (const float*)(smem + SMTAU);
#pragma unroll
        for (int mf = 0; mf < 4; mf++) {
#pragma unroll
            for (int h = 0; h < 2; h++) {
                const int gq = mtile * MT + m0 + mf * 16 + h * 8 + tq;
                if (MODE == 0) {
                    unsigned short* dst = g_Du + (size_t)gq * SN + (t0 + nb + tn2);
#pragma unroll
                    for (int nf = 0; nf < 4; nf++) {
                        float v0 = d[mf][nf][h * 2] + xv[nf].x;
                        float v1 = d[mf][nf][h * 2 + 1] + xv[nf].y;
                        unsigned short u0 = f2bf(v0), u1 = f2bf(v1);
                        *(unsigned*)(dst + nf * 8) = (unsigned)u0 | ((unsigned)u1 << 16);
                    }
                } else {
                    const float tau = tsm[m0 + mf * 16 + h * 8 + tq];
#pragma unroll
                    for (int nf = 0; nf < 4; nf++) {
                        float v0 = d[mf][nf][h * 2] + xv[nf].x;
                        float v1 = d[mf][nf][h * 2 + 1] + xv[nf].y;
                        if (v0 <= tau) {
                            int pos = atomicAdd(&g_cnt[gq], 1);
                            if (pos < CAP) g_si[(size_t)gq * CAP + pos] = t0 + nb + nf * 8 + tn2;
                        }
                        if (v1 <= tau) {
                            int pos = atomicAdd(&g_cnt[gq], 1);
                            if (pos < CAP) g_si[(size_t)gq * CAP + pos] = t0 + nb + nf * 8 + tn2 + 1;
                        }
                    }
                }
            }
        }
        __syncthreads();
    }
}

// ============================================================
// tau: radix-select 32nd smallest bf16 sample score + margin
// keys are 16-bit (bf16 bits, monotonic-transformed)
// ============================================================
__global__ void tau_kernel() {
    __shared__ unsigned short sU[SN];
    __shared__ unsigned hist[256];
    __shared__ unsigned s_prefix;
    __shared__ int s_rank;
    const int b = blockIdx.x, tid = threadIdx.x;

    for (int i = tid; i < SN / 2; i += 256) {
        unsigned w = ((const unsigned*)(g_Du + (size_t)b * SN))[i];
        unsigned short u0 = (unsigned short)w, u1 = (unsigned short)(w >> 16);
        u0 = (u0 & 0x8000u) ? (unsigned short)~u0 : (unsigned short)(u0 | 0x8000u);
        u1 = (u1 & 0x8000u) ? (unsigned short)~u1 : (unsigned short)(u1 | 0x8000u);
        ((unsigned*)sU)[i] = (unsigned)u0 | ((unsigned)u1 << 16);
    }
    if (tid == 0) { s_prefix = 0u; s_rank = NK; }
    __syncthreads();

#pragma unroll
    for (int lev = 0; lev < 2; lev++) {
        const int sh = 8 - 8 * lev;
        hist[tid] = 0;
        __syncthreads();
        const unsigned pfx = s_prefix;
        for (int i = tid; i < SN; i += 256) {
            unsigned u = sU[i];
            if (lev == 0 || (u & 0xFF00u) == pfx)
                atomicAdd(&hist[(u >> sh) & 255u], 1u);
        }
        __syncthreads();
        if (tid == 0) {
            int r = s_rank;
            unsigned cum = 0;
            for (int k = 0; k < 256; k++) {
                unsigned h = hist[k];
                if (cum + h >= (unsigned)r) {
                    s_rank = r - (int)cum;
                    s_prefix = pfx | ((unsigned)k << sh);
                    break;
                }
                cum += h;
            }
        }
        __syncthreads();
    }
    if (tid == 0) {
        unsigned short u = (unsigned short)s_prefix;
        unsigned short bb = (u & 0x8000u) ? (unsigned short)(u ^ 0x8000u) : (unsigned short)~u;
        g_tau[b] = __uint_as_float((unsigned)bb << 16) + MARGIN;
    }
}

// ============================================================
// rescore: exact fp32 score per survivor (warp per survivor)
// ============================================================
__global__ void rescore_kernel(const float* __restrict__ xq, const float* __restrict__ Xd) {
    __shared__ float xs[NF];
    const int b = blockIdx.x, tid = threadIdx.x;
    if (tid < NF) xs[tid] = xq[(size_t)b * NF + tid];
    __syncthreads();
    int c = g_cnt[b]; if (c > CAP) c = CAP;
    const int w = tid >> 5, lane = tid & 31;
    float2 xv = *(const float2*)(xs + 2 * lane);
    for (int s = w; s < c; s += 8) {
        int n = g_si[(size_t)b * CAP + s];
        float2 Xv = *(const float2*)(Xd + (size_t)n * NF + 2 * lane);
        float p = xv.x * Xv.x + xv.y * Xv.y;
#pragma unroll
        for (int off = 16; off > 0; off >>= 1) p += __shfl_xor_sync(0xffffffffu, p, off);
        if (lane == 0) g_sv[(size_t)b * CAP + s] = g_xxp[n] - 2.f * p;
    }
}

// ============================================================
// select: exact top-32 from survivors, (val, idx) tie-break
// ============================================================
__global__ void select_kernel() {
    __shared__ float sv[CAP];
    __shared__ int si[CAP];
    __shared__ float rv[8];
    __shared__ int ri[8], rp[8];
    const int b = blockIdx.x, tid = threadIdx.x;
    int c = g_cnt[b]; if (c > CAP) c = CAP;
    const int cpad = (c + 255) & ~255;
    for (int i = tid; i < cpad; i += 256) {
        sv[i] = (i < c) ? g_sv[(size_t)b * CAP + i] : BIGV;
        si[i] = (i < c) ? g_si[(size_t)b * CAP + i] : 0x7FFFFFFF;
    }
    __syncthreads();
    for (int r = 0; r < NK; r++) {
        float bv = BIGV; int bi = 0x7FFFFFFF; int bp = 0;
        for (int i = tid; i < cpad; i += 256) {
            float v = sv[i]; int ix = si[i];
            if (v < bv || (v == bv && ix < bi)) { bv = v; bi = ix; bp = i; }
        }
#pragma unroll
        for (int off = 16; off > 0; off >>= 1) {
            float ov = __shfl_down_sync(0xffffffffu, bv, off);
            int oi = __shfl_down_sync(0xffffffffu, bi, off);
            int op = __shfl_down_sync(0xffffffffu, bp, off);
            if (ov < bv || (ov == bv && oi < bi)) { bv = ov; bi = oi; bp = op; }
        }
        if ((tid & 31) == 0) { rv[tid >> 5] = bv; ri[tid >> 5] = bi; rp[tid >> 5] = bp; }
        __syncthreads();
        if (tid == 0) {
            for (int wi = 1; wi < 8; wi++)
                if (rv[wi] < rv[0] || (rv[wi] == rv[0] && ri[wi] < ri[0])) {
                    rv[0] = rv[wi]; ri[0] = ri[wi]; rp[0] = rp[wi];
                }
            g_topk[b * NK + r] = ri[0];
            sv[rp[0]] = BIGV; si[rp[0]] = 0x7FFFFFFF;
        }
        __syncthreads();
    }
}

// ============================================================
// mlp: gather neighbors + gated MLP head (one block per query)
// ============================================================
__global__ void mlp_kernel(const float* __restrict__ xq, const float* __restrict__ Xd,
                           const float* __restrict__ yv, const float* __restrict__ Wg,
                           const float* __restrict__ bg, const float* __restrict__ W1,
                           const float* __restrict__ b1, const float* __restrict__ Wl,
                           const float* __restrict__ bl, float* __restrict__ out) {
    __shared__ float nfs[NK * 65];
    __shared__ float Wgs[65 * NC];
    __shared__ float gs[NK * NC];
    __shared__ float xa[NF + NC];
    __shared__ float red[4];
    __shared__ int idx[NK];
    const int b = blockIdx.x, tid = threadIdx.x;

    if (tid < NK) idx[tid] = g_topk[b * NK + tid];
    for (int i = tid; i < 65 * NC; i += 128) Wgs[i] = Wg[i];
    __syncthreads();
    for (int i = tid; i < NK * NF; i += 128) {
        int k = i >> 6, f = i & 63;
        nfs[k * 65 + f] = Xd[(size_t)idx[k] * NF + f];
    }
    if (tid < NK) nfs[tid * 65 + 64] = yv[idx[tid]];
    __syncthreads();

    {
        int k = tid & 31, c0 = (tid >> 5) * 4;
        float a0 = bg[c0], a1 = bg[c0 + 1], a2 = bg[c0 + 2], a3 = bg[c0 + 3];
#pragma unroll 5
        for (int j = 0; j < 65; j++) {
            float v = nfs[k * 65 + j];
            a0 += v * Wgs[j * NC + c0];
            a1 += v * Wgs[j * NC + c0 + 1];
            a2 += v * Wgs[j * NC + c0 + 2];
            a3 += v * Wgs[j * NC + c0 + 3];
        }
        gs[k * NC + c0] = tanhf(a0);
        gs[k * NC + c0 + 1] = tanhf(a1);
        gs[k * NC + c0 + 2] = tanhf(a2);
        gs[k * NC + c0 + 3] = tanhf(a3);
    }
    __syncthreads();
    if (tid < NF) {
        xa[tid] = xq[(size_t)b * NF + tid];
    } else if (tid < NF + NC) {
        int c = tid - NF;
        float s = 0.f;
#pragma unroll
        for (int k = 0; k < NK; k++) s += gs[k * NC + c];
        xa[tid] = s;
    }
    __syncthreads();

    float s = b1[tid];
#pragma unroll 8
    for (int i = 0; i < NF + NC; i++) s += xa[i] * W1[i * NH + tid];
    float oh = tanhf(s);
    float r = oh * Wl[tid];
#pragma unroll
    for (int off = 16; off > 0; off >>= 1) r += __shfl_down_sync(0xffffffffu, r, off);
    if ((tid & 31) == 0) red[tid >> 5] = r;
    __syncthreads();
    if (tid == 0) {
        float t = red[0] + red[1] + red[2] + red[3] + bl[0];
        out[b] = 1.f / (1.f + expf(-t));
    }
}

// ============================================================
extern "C" void kernel_launch(void* const* d_in, const int* in_sizes, int n_in,
                              void* d_out, int out_size) {
    (void)in_sizes; (void)n_in; (void)out_size;
    const float* xq = (const float*)d_in[0];
    const float* Xd = (const float*)d_in[1];
    const float* yv = (const float*)d_in[2];
    const float* Wg = (const float*)d_in[3];
    const float* bg = (const float*)d_in[4];
    const float* W1 = (const float*)d_in[5];
    const float* b1 = (const float*)d_in[6];
    const float* Wl = (const float*)d_in[7];
    const float* bl = (const float*)d_in[8];
    float* out = (float*)d_out;

    cudaFuncSetAttribute(mma_kernel<0, SAMPLE_TILES>, cudaFuncAttributeMaxDynamicSharedMemorySize, SM_TOTAL);
    cudaFuncSetAttribute(mma_kernel<1, MAIN_TILES>, cudaFuncAttributeMaxDynamicSharedMemorySize, SM_TOTAL);

    prep_x_kernel<<<NDPAD / 64, 256>>>(Xd);
    prep_q_kernel<<<128, 256>>>(xq);
    zero_kernel<<<4, 256>>>();
    mma_kernel<0, SAMPLE_TILES><<<dim3(NQ / MT, SAMPLE_SLICES), 256, SM_TOTAL>>>();
    tau_kernel<<<NQ, 256>>>();
    mma_kernel<1, MAIN_TILES><<<dim3(NQ / MT, NSL), 256, SM_TOTAL>>>();
    rescore_kernel<<<NQ, 256>>>(xq, Xd);
    select_kernel<<<NQ, 256>>>();
    mlp_kernel<<<NQ, 128>>>(xq, Xd, yv, Wg, bg, W1, b1, Wl, bl, out);
}

// round 6
// speedup vs baseline: 13.9539x; 1.1605x over previous
#include <cuda_runtime.h>
#include <cuda_bf16.h>
#include <math.h>
#include <stdint.h>

// ---------------- problem constants ----------------
#define NQ 1024
#define ND 200000
#define NF 64
#define NK 32
#define NC 16
#define NH 128

#define MT 128           // queries per CTA
#define NT 64            // points per tile
#define NSL 56           // main-pass slices -> grid (8,56)=448 CTAs (~148*3)
#define MAIN_TILES 56    // 56*56*64 = 200704 >= 200000
#define NDPAD 200704
#define SN 16384         // sample size
#define SAMPLE_SLICES 64
#define SAMPLE_TILES 4   // 64*4*64 = 16384
#define CAP 4096
#define MARGIN 4.0f      // 2*E_mma + E_bf16store safety margin
#define BIGV 3.0e38f

// ---------------- static device scratch ----------------
__device__ float          g_xxp[NDPAD];
__device__ __nv_bfloat16  g_Xb[(size_t)NDPAD * NF];
__device__ __nv_bfloat16  g_Qb[(size_t)NQ * NF];
__device__ unsigned short g_Du[(size_t)NQ * SN];   // bf16 sample scores
__device__ float          g_tau[NQ];
__device__ int            g_cnt[NQ];
__device__ float          g_sv[(size_t)NQ * CAP];
__device__ int            g_si[(size_t)NQ * CAP];
__device__ int            g_topk[NQ * NK];

// ---------------- helpers ----------------
__device__ __forceinline__ uint32_t smem_u32(const void* p) {
    uint32_t a;
    asm("{ .reg .u64 t; cvta.to.shared.u64 t, %1; cvt.u32.u64 %0, t; }" : "=r"(a) : "l"(p));
    return a;
}
#define SWZ128(o) ((o) ^ (((o) >> 3) & 0x70))

__device__ __forceinline__ void cpa16(uint32_t d, const void* s) {
    asm volatile("cp.async.cg.shared.global [%0], [%1], 16;" :: "r"(d), "l"(s) : "memory");
}
#define CPA_COMMIT() asm volatile("cp.async.commit_group;" ::: "memory")

__device__ __forceinline__ void ldsm4(uint32_t* r, uint32_t a) {
    asm volatile("ldmatrix.sync.aligned.m8n8.x4.shared.b16 {%0,%1,%2,%3}, [%4];"
                 : "=r"(r[0]), "=r"(r[1]), "=r"(r[2]), "=r"(r[3]) : "r"(a));
}
__device__ __forceinline__ void mma16816(float* d, const uint32_t* a, const uint32_t* b) {
    asm volatile(
        "mma.sync.aligned.m16n8k16.row.col.f32.bf16.bf16.f32 "
        "{%0,%1,%2,%3}, {%4,%5,%6,%7}, {%8,%9}, {%0,%1,%2,%3};"
        : "+f"(d[0]), "+f"(d[1]), "+f"(d[2]), "+f"(d[3])
        : "r"(a[0]), "r"(a[1]), "r"(a[2]), "r"(a[3]), "r"(b[0]), "r"(b[1]));
}
__device__ __forceinline__ unsigned short f2bf(float v) {
    __nv_bfloat16 h = __float2bfloat16(v);
    return *(unsigned short*)&h;
}

// ---------------- smem layout (bytes) ----------------
#define SMQ    0
#define SMX0   16384
#define SMX1   24576
#define SMXX0  32768
#define SMXX1  33024
#define SMTAU  33280
#define SM_TOTAL 33792

// ============================================================
// prep_x: exact fp32 norms + bf16 conversion + padding
// ============================================================
__global__ void prep_x_kernel(const float* __restrict__ Xd) {
    int r = blockIdx.x * 64 + (threadIdx.x >> 2);
    int part = threadIdx.x & 3;
    if (r >= NDPAD) return;
    uint4* dst = (uint4*)(g_Xb + (size_t)r * NF) + part * 2;
    if (r < ND) {
        const float4* row = (const float4*)(Xd + (size_t)r * NF) + part * 4;
        float4 v[4];
        float s = 0.f;
#pragma unroll
        for (int l = 0; l < 4; l++) {
            v[l] = row[l];
            s += v[l].x * v[l].x + v[l].y * v[l].y + v[l].z * v[l].z + v[l].w * v[l].w;
        }
        s += __shfl_xor_sync(0xffffffffu, s, 1);
        s += __shfl_xor_sync(0xffffffffu, s, 2);
        if (part == 0) g_xxp[r] = s;
        unsigned u[8];
#pragma unroll
        for (int l = 0; l < 4; l++) {
            __nv_bfloat162 h0 = __floats2bfloat162_rn(v[l].x, v[l].y);
            __nv_bfloat162 h1 = __floats2bfloat162_rn(v[l].z, v[l].w);
            u[l * 2]     = *(unsigned*)&h0;
            u[l * 2 + 1] = *(unsigned*)&h1;
        }
        dst[0] = make_uint4(u[0], u[1], u[2], u[3]);
        dst[1] = make_uint4(u[4], u[5], u[6], u[7]);
    } else {
        if (part == 0) g_xxp[r] = BIGV;
        uint4 z = make_uint4(0, 0, 0, 0);
        dst[0] = z; dst[1] = z;
    }
}

// prep_q: g_Qb = bf16(-2 * x)
__global__ void prep_q_kernel(const float* __restrict__ xq) {
    int i = blockIdx.x * 256 + threadIdx.x;
    float2 v = ((const float2*)xq)[i];
    __nv_bfloat162 h = __floats2bfloat162_rn(-2.f * v.x, -2.f * v.y);
    ((__nv_bfloat162*)g_Qb)[i] = h;
}

__global__ void zero_kernel() {
    int i = blockIdx.x * 256 + threadIdx.x;
    if (i < NQ) g_cnt[i] = 0;
}

// ============================================================
// MMA kernel: warp tile 32q x 32n, CTA tile 128q x 64n.
// Q(A) fragments hoisted into registers for the whole slice.
// MODE 0: write bf16 approx scores of sample region to g_Du
// MODE 1: filter vs g_tau, append survivor indices
// ============================================================
template <int MODE, int NTILES>
__global__ void __launch_bounds__(256, 3)
mma_kernel() {
    extern __shared__ char smem[];
    const uint32_t sb = smem_u32(smem);
    const int tid = threadIdx.x;
    const int lane = tid & 31;
    const int wid = tid >> 5;
    const int mtile = blockIdx.x;
    const int base = blockIdx.y * NTILES * NT;

    // load Q tile into swizzled smem (128 rows x 128B)
    {
        const uint4* qsrc = (const uint4*)(g_Qb + (size_t)mtile * MT * NF);
#pragma unroll
        for (int c = 0; c < 4; c++) {
            int ch = tid + c * 256;
            int row = ch >> 3, col = ch & 7;
            *(uint4*)(smem + SMQ + SWZ128(row * 128 + col * 16)) = qsrc[ch];
        }
    }
    if (MODE == 1 && tid < MT) ((float*)(smem + SMTAU))[tid] = g_tau[mtile * MT + tid];

    // async-load X tile 0 (64 rows x 128B) + norms
    {
        const uint4* xs = (const uint4*)(g_Xb + (size_t)base * NF);
#pragma unroll
        for (int c = 0; c < 2; c++) {
            int ch = tid + c * 256;
            int row = ch >> 3, col = ch & 7;
            cpa16(sb + SMX0 + SWZ128(row * 128 + col * 16), xs + ch);
        }
        if (tid < 16) cpa16(sb + SMXX0 + tid * 16, g_xxp + base + tid * 4);
        CPA_COMMIT();
    }
    __syncthreads();

    const int wr = wid >> 1;          // 0..3 : q-row block of 32
    const int wc = wid & 1;           // 0..1 : n-col block of 32
    const int m0 = wr * 32;
    const int nb = wc * 32;
    const int tq = lane >> 2;         // row within 8
    const int tn2 = (lane & 3) * 2;   // col pair within 8

    // ldmatrix lane addressing
    const int a_row = lane & 15, a_kh = lane >> 4;
    const int b_row = (lane & 7) | ((lane >> 4) << 3), b_kh = (lane >> 3) & 1;

    // hoist A (Q) fragments: [ks][mf*4 + i]  (32 regs)
    uint32_t afr[4][8];
#pragma unroll
    for (int ks = 0; ks < 4; ks++)
#pragma unroll
        for (int mf = 0; mf < 2; mf++) {
            uint32_t addr = sb + SMQ +
                SWZ128((m0 + mf * 16 + a_row) * 128 + ks * 32 + a_kh * 16);
            ldsm4(&afr[ks][mf * 4], addr);
        }

    for (int t = 0; t < NTILES; t++) {
        const int t0 = base + t * NT;
        const uint32_t xb  = (t & 1) ? SMX1 : SMX0;
        const uint32_t xxb = (t & 1) ? SMXX1 : SMXX0;

        // prefetch t+1 into the other buffer
        if (t + 1 < NTILES) {
            const uint4* xs = (const uint4*)(g_Xb + (size_t)(t0 + NT) * NF);
            uint32_t dxb  = (t & 1) ? SMX0 : SMX1;
            uint32_t dxxb = (t & 1) ? SMXX0 : SMXX1;
#pragma unroll
            for (int c = 0; c < 2; c++) {
                int ch = tid + c * 256;
                int row = ch >> 3, col = ch & 7;
                cpa16(sb + dxb + SWZ128(row * 128 + col * 16), xs + ch);
            }
            if (tid < 16) cpa16(sb + dxxb + tid * 16, g_xxp + t0 + NT + tid * 4);
            CPA_COMMIT();
            asm volatile("cp.async.wait_group 1;" ::: "memory");
        } else {
            asm volatile("cp.async.wait_group 0;" ::: "memory");
        }
        __syncthreads();

        float d[2][4][4];
#pragma unroll
        for (int i = 0; i < 2; i++)
#pragma unroll
            for (int j = 0; j < 4; j++)
#pragma unroll
                for (int k = 0; k < 4; k++) d[i][j][k] = 0.f;

#pragma unroll
        for (int ks = 0; ks < 4; ks++) {
            uint32_t b[4][2];
#pragma unroll
            for (int h = 0; h < 2; h++) {
                uint32_t r[4];
                uint32_t addr = sb + xb +
                    SWZ128((nb + h * 16 + b_row) * 128 + ks * 32 + b_kh * 16);
                ldsm4(r, addr);
                b[h * 2][0] = r[0]; b[h * 2][1] = r[1];
                b[h * 2 + 1][0] = r[2]; b[h * 2 + 1][1] = r[3];
            }
#pragma unroll
            for (int mf = 0; mf < 2; mf++)
#pragma unroll
                for (int nf = 0; nf < 4; nf++)
                    mma16816(d[mf][nf], &afr[ks][mf * 4], b[nf]);
        }

        // epilogue
        const float* xxs = (const float*)(smem + xxb);
        float2 xv[4];
#pragma unroll
        for (int nf = 0; nf < 4; nf++) xv[nf] = *(const float2*)(xxs + nb + nf * 8 + tn2);

        const float* tsm = (const float*)(smem + SMTAU);
#pragma unroll
        for (int mf = 0; mf < 2; mf++) {
#pragma unroll
            for (int h = 0; h < 2; h++) {
                const int gq = mtile * MT + m0 + mf * 16 + h * 8 + tq;
                if (MODE == 0) {
                    unsigned short* dst = g_Du + (size_t)gq * SN + (t0 + nb + tn2);
#pragma unroll
                    for (int nf = 0; nf < 4; nf++) {
                        float v0 = d[mf][nf][h * 2] + xv[nf].x;
                        float v1 = d[mf][nf][h * 2 + 1] + xv[nf].y;
                        unsigned short u0 = f2bf(v0), u1 = f2bf(v1);
                        *(unsigned*)(dst + nf * 8) = (unsigned)u0 | ((unsigned)u1 << 16);
                    }
                } else {
                    const float tau = tsm[m0 + mf * 16 + h * 8 + tq];
#pragma unroll
                    for (int nf = 0; nf < 4; nf++) {
                        float v0 = d[mf][nf][h * 2] + xv[nf].x;
                        float v1 = d[mf][nf][h * 2 + 1] + xv[nf].y;
                        if (v0 <= tau) {
                            int pos = atomicAdd(&g_cnt[gq], 1);
                            if (pos < CAP) g_si[(size_t)gq * CAP + pos] = t0 + nb + nf * 8 + tn2;
                        }
                        if (v1 <= tau) {
                            int pos = atomicAdd(&g_cnt[gq], 1);
                            if (pos < CAP) g_si[(size_t)gq * CAP + pos] = t0 + nb + nf * 8 + tn2 + 1;
                        }
                    }
                }
            }
        }
        __syncthreads();
    }
}

// ============================================================
// tau: radix-select 32nd smallest bf16 sample score + margin
// ============================================================
__global__ void tau_kernel() {
    __shared__ unsigned short sU[SN];
    __shared__ unsigned hist[256];
    __shared__ unsigned s_prefix;
    __shared__ int s_rank;
    const int b = blockIdx.x, tid = threadIdx.x;

    for (int i = tid; i < SN / 2; i += 256) {
        unsigned w = ((const unsigned*)(g_Du + (size_t)b * SN))[i];
        unsigned short u0 = (unsigned short)w, u1 = (unsigned short)(w >> 16);
        u0 = (u0 & 0x8000u) ? (unsigned short)~u0 : (unsigned short)(u0 | 0x8000u);
        u1 = (u1 & 0x8000u) ? (unsigned short)~u1 : (unsigned short)(u1 | 0x8000u);
        ((unsigned*)sU)[i] = (unsigned)u0 | ((unsigned)u1 << 16);
    }
    if (tid == 0) { s_prefix = 0u; s_rank = NK; }
    __syncthreads();

#pragma unroll
    for (int lev = 0; lev < 2; lev++) {
        const int sh = 8 - 8 * lev;
        hist[tid] = 0;
        __syncthreads();
        const unsigned pfx = s_prefix;
        for (int i = tid; i < SN; i += 256) {
            unsigned u = sU[i];
            if (lev == 0 || (u & 0xFF00u) == pfx)
                atomicAdd(&hist[(u >> sh) & 255u], 1u);
        }
        __syncthreads();
        if (tid == 0) {
            int r = s_rank;
            unsigned cum = 0;
            for (int k = 0; k < 256; k++) {
                unsigned h = hist[k];
                if (cum + h >= (unsigned)r) {
                    s_rank = r - (int)cum;
                    s_prefix = pfx | ((unsigned)k << sh);
                    break;
                }
                cum += h;
            }
        }
        __syncthreads();
    }
    if (tid == 0) {
        unsigned short u = (unsigned short)s_prefix;
        unsigned short bb = (u & 0x8000u) ? (unsigned short)(u ^ 0x8000u) : (unsigned short)~u;
        g_tau[b] = __uint_as_float((unsigned)bb << 16) + MARGIN;
    }
}

// ============================================================
// rescore: exact fp32 score per survivor (warp per survivor)
// ============================================================
__global__ void rescore_kernel(const float* __restrict__ xq, const float* __restrict__ Xd) {
    __shared__ float xs[NF];
    const int b = blockIdx.x, tid = threadIdx.x;
    if (tid < NF) xs[tid] = xq[(size_t)b * NF + tid];
    __syncthreads();
    int c = g_cnt[b]; if (c > CAP) c = CAP;
    const int w = tid >> 5, lane = tid & 31;
    float2 xv = *(const float2*)(xs + 2 * lane);
    for (int s = w; s < c; s += 8) {
        int n = g_si[(size_t)b * CAP + s];
        float2 Xv = *(const float2*)(Xd + (size_t)n * NF + 2 * lane);
        float p = xv.x * Xv.x + xv.y * Xv.y;
#pragma unroll
        for (int off = 16; off > 0; off >>= 1) p += __shfl_xor_sync(0xffffffffu, p, off);
        if (lane == 0) g_sv[(size_t)b * CAP + s] = g_xxp[n] - 2.f * p;
    }
}

// ============================================================
// select: exact top-32 from survivors, (val, idx) tie-break
// ============================================================
__global__ void select_kernel() {
    __shared__ float sv[CAP];
    __shared__ int si[CAP];
    __shared__ float rv[8];
    __shared__ int ri[8], rp[8];
    const int b = blockIdx.x, tid = threadIdx.x;
    int c = g_cnt[b]; if (c > CAP) c = CAP;
    const int cpad = (c + 255) & ~255;
    for (int i = tid; i < cpad; i += 256) {
        sv[i] = (i < c) ? g_sv[(size_t)b * CAP + i] : BIGV;
        si[i] = (i < c) ? g_si[(size_t)b * CAP + i] : 0x7FFFFFFF;
    }
    __syncthreads();
    for (int r = 0; r < NK; r++) {
        float bv = BIGV; int bi = 0x7FFFFFFF; int bp = 0;
        for (int i = tid; i < cpad; i += 256) {
            float v = sv[i]; int ix = si[i];
            if (v < bv || (v == bv && ix < bi)) { bv = v; bi = ix; bp = i; }
        }
#pragma unroll
        for (int off = 16; off > 0; off >>= 1) {
            float ov = __shfl_down_sync(0xffffffffu, bv, off);
            int oi = __shfl_down_sync(0xffffffffu, bi, off);
            int op = __shfl_down_sync(0xffffffffu, bp, off);
            if (ov < bv || (ov == bv && oi < bi)) { bv = ov; bi = oi; bp = op; }
        }
        if ((tid & 31) == 0) { rv[tid >> 5] = bv; ri[tid >> 5] = bi; rp[tid >> 5] = bp; }
        __syncthreads();
        if (tid == 0) {
            for (int wi = 1; wi < 8; wi++)
                if (rv[wi] < rv[0] || (rv[wi] == rv[0] && ri[wi] < ri[0])) {
                    rv[0] = rv[wi]; ri[0] = ri[wi]; rp[0] = rp[wi];
                }
            g_topk[b * NK + r] = ri[0];
            sv[rp[0]] = BIGV; si[rp[0]] = 0x7FFFFFFF;
        }
        __syncthreads();
    }
}

// ============================================================
// mlp: gather neighbors + gated MLP head (one block per query)
// ============================================================
__global__ void mlp_kernel(const float* __restrict__ xq, const float* __restrict__ Xd,
                           const float* __restrict__ yv, const float* __restrict__ Wg,
                           const float* __restrict__ bg, const float* __restrict__ W1,
                           const float* __restrict__ b1, const float* __restrict__ Wl,
                           const float* __restrict__ bl, float* __restrict__ out) {
    __shared__ float nfs[NK * 65];
    __shared__ float Wgs[65 * NC];
    __shared__ float gs[NK * NC];
    __shared__ float xa[NF + NC];
    __shared__ float red[4];
    __shared__ int idx[NK];
    const int b = blockIdx.x, tid = threadIdx.x;

    if (tid < NK) idx[tid] = g_topk[b * NK + tid];
    for (int i = tid; i < 65 * NC; i += 128) Wgs[i] = Wg[i];
    __syncthreads();
    for (int i = tid; i < NK * NF; i += 128) {
        int k = i >> 6, f = i & 63;
        nfs[k * 65 + f] = Xd[(size_t)idx[k] * NF + f];
    }
    if (tid < NK) nfs[tid * 65 + 64] = yv[idx[tid]];
    __syncthreads();

    {
        int k = tid & 31, c0 = (tid >> 5) * 4;
        float a0 = bg[c0], a1 = bg[c0 + 1], a2 = bg[c0 + 2], a3 = bg[c0 + 3];
#pragma unroll 5
        for (int j = 0; j < 65; j++) {
            float v = nfs[k * 65 + j];
            a0 += v * Wgs[j * NC + c0];
            a1 += v * Wgs[j * NC + c0 + 1];
            a2 += v * Wgs[j * NC + c0 + 2];
            a3 += v * Wgs[j * NC + c0 + 3];
        }
        gs[k * NC + c0] = tanhf(a0);
        gs[k * NC + c0 + 1] = tanhf(a1);
        gs[k * NC + c0 + 2] = tanhf(a2);
        gs[k * NC + c0 + 3] = tanhf(a3);
    }
    __syncthreads();
    if (tid < NF) {
        xa[tid] = xq[(size_t)b * NF + tid];
    } else if (tid < NF + NC) {
        int c = tid - NF;
        float s = 0.f;
#pragma unroll
        for (int k = 0; k < NK; k++) s += gs[k * NC + c];
        xa[tid] = s;
    }
    __syncthreads();

    float s = b1[tid];
#pragma unroll 8
    for (int i = 0; i < NF + NC; i++) s += xa[i] * W1[i * NH + tid];
    float oh = tanhf(s);
    float r = oh * Wl[tid];
#pragma unroll
    for (int off = 16; off > 0; off >>= 1) r += __shfl_down_sync(0xffffffffu, r, off);
    if ((tid & 31) == 0) red[tid >> 5] = r;
    __syncthreads();
    if (tid == 0) {
        float t = red[0] + red[1] + red[2] + red[3] + bl[0];
        out[b] = 1.f / (1.f + expf(-t));
    }
}

// ============================================================
extern "C" void kernel_launch(void* const* d_in, const int* in_sizes, int n_in,
                              void* d_out, int out_size) {
    (void)in_sizes; (void)n_in; (void)out_size;
    const float* xq = (const float*)d_in[0];
    const float* Xd = (const float*)d_in[1];
    const float* yv = (const float*)d_in[2];
    const float* Wg = (const float*)d_in[3];
    const float* bg = (const float*)d_in[4];
    const float* W1 = (const float*)d_in[5];
    const float* b1 = (const float*)d_in[6];
    const float* Wl = (const float*)d_in[7];
    const float* bl = (const float*)d_in[8];
    float* out = (float*)d_out;

    cudaFuncSetAttribute(mma_kernel<0, SAMPLE_TILES>, cudaFuncAttributeMaxDynamicSharedMemorySize, SM_TOTAL);
    cudaFuncSetAttribute(mma_kernel<1, MAIN_TILES>, cudaFuncAttributeMaxDynamicSharedMemorySize, SM_TOTAL);

    prep_x_kernel<<<(NDPAD + 63) / 64, 256>>>(Xd);
    prep_q_kernel<<<128, 256>>>(xq);
    zero_kernel<<<4, 256>>>();
    mma_kernel<0, SAMPLE_TILES><<<dim3(NQ / MT, SAMPLE_SLICES), 256, SM_TOTAL>>>();
    tau_kernel<<<NQ, 256>>>();
    mma_kernel<1, MAIN_TILES><<<dim3(NQ / MT, NSL), 256, SM_TOTAL>>>();
    rescore_kernel<<<NQ, 256>>>(xq, Xd);
    select_kernel<<<NQ, 256>>>();
    mlp_kernel<<<NQ, 128>>>(xq, Xd, yv, Wg, bg, W1, b1, Wl, bl, out);
}

// round 7
// speedup vs baseline: 14.5608x; 1.0435x over previous
#include <cuda_runtime.h>
#include <cuda_bf16.h>
#include <math.h>
#include <stdint.h>

// ---------------- problem constants ----------------
#define NQ 1024
#define ND 200000
#define NF 64
#define NK 32
#define NC 16
#define NH 128

#define MT 128           // queries per CTA
#define NT 128           // points per smem stage
#define NSL 56           // main-pass slices -> grid (8,56)=448 CTAs (~148*3)
#define MAIN_TILES 28    // 56*28*128 = 200704 >= 200000
#define NDPAD 200704
#define SN 16384         // sample size
#define SAMPLE_SLICES 32
#define SAMPLE_TILES 4   // 32*4*128 = 16384
#define CAP 4096
#define MARGIN 4.0f      // mma approx + bf16-store safety margin
#define BIGV 3.0e38f

// ---------------- static device scratch ----------------
__device__ float          g_xxp[NDPAD];
__device__ __nv_bfloat16  g_Xb[(size_t)NDPAD * NF];
__device__ __nv_bfloat16  g_Qb[(size_t)NQ * NF];
__device__ unsigned short g_Du[(size_t)NQ * SN];   // bf16 sample scores
__device__ float          g_tau[NQ];
__device__ int            g_cnt[NQ];
__device__ float          g_sv[(size_t)NQ * CAP];
__device__ int            g_si[(size_t)NQ * CAP];
__device__ int            g_topk[NQ * NK];

// ---------------- helpers ----------------
__device__ __forceinline__ uint32_t smem_u32(const void* p) {
    uint32_t a;
    asm("{ .reg .u64 t; cvta.to.shared.u64 t, %1; cvt.u32.u64 %0, t; }" : "=r"(a) : "l"(p));
    return a;
}
#define SWZ128(o) ((o) ^ (((o) >> 3) & 0x70))

__device__ __forceinline__ void cpa16(uint32_t d, const void* s) {
    asm volatile("cp.async.cg.shared.global [%0], [%1], 16;" :: "r"(d), "l"(s) : "memory");
}
#define CPA_COMMIT() asm volatile("cp.async.commit_group;" ::: "memory")
#define CPA_WAIT1()  asm volatile("cp.async.wait_group 1;" ::: "memory")

__device__ __forceinline__ void ldsm4(uint32_t* r, uint32_t a) {
    asm volatile("ldmatrix.sync.aligned.m8n8.x4.shared.b16 {%0,%1,%2,%3}, [%4];"
                 : "=r"(r[0]), "=r"(r[1]), "=r"(r[2]), "=r"(r[3]) : "r"(a));
}
__device__ __forceinline__ void mma16816(float* d, const uint32_t* a, const uint32_t* b) {
    asm volatile(
        "mma.sync.aligned.m16n8k16.row.col.f32.bf16.bf16.f32 "
        "{%0,%1,%2,%3}, {%4,%5,%6,%7}, {%8,%9}, {%0,%1,%2,%3};"
        : "+f"(d[0]), "+f"(d[1]), "+f"(d[2]), "+f"(d[3])
        : "r"(a[0]), "r"(a[1]), "r"(a[2]), "r"(a[3]), "r"(b[0]), "r"(b[1]));
}
__device__ __forceinline__ unsigned short f2bf(float v) {
    __nv_bfloat16 h = __float2bfloat16(v);
    return *(unsigned short*)&h;
}

// ---------------- smem layout (bytes) ----------------
// Q: 16KB, X stages: 3 x 16KB, norms: 3 x 512B, tau: 512B
#define SMQ     0
#define SMX(s)  (16384 + (s) * 16384)
#define SMXX(s) (65536 + (s) * 512)
#define SMTAU   67072
#define SM_TOTAL 67584

// ============================================================
// prep_x: exact fp32 norms + bf16 conversion + padding
// ============================================================
__global__ void prep_x_kernel(const float* __restrict__ Xd) {
    int r = blockIdx.x * 64 + (threadIdx.x >> 2);
    int part = threadIdx.x & 3;
    if (r >= NDPAD) return;
    uint4* dst = (uint4*)(g_Xb + (size_t)r * NF) + part * 2;
    if (r < ND) {
        const float4* row = (const float4*)(Xd + (size_t)r * NF) + part * 4;
        float4 v[4];
        float s = 0.f;
#pragma unroll
        for (int l = 0; l < 4; l++) {
            v[l] = row[l];
            s += v[l].x * v[l].x + v[l].y * v[l].y + v[l].z * v[l].z + v[l].w * v[l].w;
        }
        s += __shfl_xor_sync(0xffffffffu, s, 1);
        s += __shfl_xor_sync(0xffffffffu, s, 2);
        if (part == 0) g_xxp[r] = s;
        unsigned u[8];
#pragma unroll
        for (int l = 0; l < 4; l++) {
            __nv_bfloat162 h0 = __floats2bfloat162_rn(v[l].x, v[l].y);
            __nv_bfloat162 h1 = __floats2bfloat162_rn(v[l].z, v[l].w);
            u[l * 2]     = *(unsigned*)&h0;
            u[l * 2 + 1] = *(unsigned*)&h1;
        }
        dst[0] = make_uint4(u[0], u[1], u[2], u[3]);
        dst[1] = make_uint4(u[4], u[5], u[6], u[7]);
    } else {
        if (part == 0) g_xxp[r] = BIGV;
        uint4 z = make_uint4(0, 0, 0, 0);
        dst[0] = z; dst[1] = z;
    }
}

// prep_q: g_Qb = bf16(-2 * x)
__global__ void prep_q_kernel(const float* __restrict__ xq) {
    int i = blockIdx.x * 256 + threadIdx.x;
    float2 v = ((const float2*)xq)[i];
    __nv_bfloat162 h = __floats2bfloat162_rn(-2.f * v.x, -2.f * v.y);
    ((__nv_bfloat162*)g_Qb)[i] = h;
}

__global__ void zero_kernel() {
    int i = blockIdx.x * 256 + threadIdx.x;
    if (i < NQ) g_cnt[i] = 0;
}

// ============================================================
// MMA kernel: warp tile 32q x 32n, CTA tile 128q x 128n/stage,
// 3-stage cp.async ring, ONE __syncthreads per stage.
// A (Q) fragments hoisted into registers for the whole slice.
// MODE 0: write bf16 approx scores of sample region to g_Du
// MODE 1: filter vs g_tau, append survivor indices
// ============================================================
template <int MODE, int NTILES>
__global__ void __launch_bounds__(256, 3)
mma_kernel() {
    extern __shared__ char smem[];
    const uint32_t sb = smem_u32(smem);
    const int tid = threadIdx.x;
    const int lane = tid & 31;
    const int wid = tid >> 5;
    const int mtile = blockIdx.x;
    const int base = blockIdx.y * NTILES * NT;

    // load Q tile into swizzled smem (128 rows x 128B)
    {
        const uint4* qsrc = (const uint4*)(g_Qb + (size_t)mtile * MT * NF);
#pragma unroll
        for (int c = 0; c < 4; c++) {
            int ch = tid + c * 256;
            int row = ch >> 3, col = ch & 7;
            *(uint4*)(smem + SMQ + SWZ128(row * 128 + col * 16)) = qsrc[ch];
        }
    }
    if (MODE == 1 && tid < MT) ((float*)(smem + SMTAU))[tid] = g_tau[mtile * MT + tid];

    // prologue: issue stages 0 and 1
#pragma unroll
    for (int s = 0; s < 2; s++) {
        if (s < NTILES) {
            const uint4* xs = (const uint4*)(g_Xb + (size_t)(base + s * NT) * NF);
#pragma unroll
            for (int c = 0; c < 4; c++) {
                int ch = tid + c * 256;
                int row = ch >> 3, col = ch & 7;
                cpa16(sb + SMX(s) + SWZ128(row * 128 + col * 16), xs + ch);
            }
            if (tid < 32) cpa16(sb + SMXX(s) + tid * 16, g_xxp + base + s * NT + tid * 4);
        }
        CPA_COMMIT();
    }
    __syncthreads();   // Q (and tau) visible

    const int wr = wid >> 1;          // 0..3 : q-row block of 32
    const int wc = wid & 1;           // 0..1 : n-col block of 32 (within a 64 half)
    const int m0 = wr * 32;
    const int nb = wc * 32;
    const int tq = lane >> 2;         // row within 8
    const int tn2 = (lane & 3) * 2;   // col pair within 8

    // ldmatrix lane addressing
    const int a_row = lane & 15, a_kh = lane >> 4;
    const int b_row = (lane & 7) | ((lane >> 4) << 3), b_kh = (lane >> 3) & 1;

    // hoist A (Q) fragments: [ks][mf*4 + i]  (32 regs)
    uint32_t afr[4][8];
#pragma unroll
    for (int ks = 0; ks < 4; ks++)
#pragma unroll
        for (int mf = 0; mf < 2; mf++) {
            uint32_t addr = sb + SMQ +
                SWZ128((m0 + mf * 16 + a_row) * 128 + ks * 32 + a_kh * 16);
            ldsm4(&afr[ks][mf * 4], addr);
        }

    for (int t = 0; t < NTILES; t++) {
        const int t0 = base + t * NT;
        const int st = t % 3;
        const uint32_t xb  = SMX(st);
        const uint32_t xxb = SMXX(st);

        CPA_WAIT1();          // stage t complete (only stage t+1 may be pending)
        __syncthreads();      // all warps done with stage (t+2)%3's previous life

        // issue prefetch of stage t+2 (after the barrier -> no overwrite hazard)
        if (t + 2 < NTILES) {
            const int ps = (t + 2) % 3;
            const uint4* xs = (const uint4*)(g_Xb + (size_t)(t0 + 2 * NT) * NF);
#pragma unroll
            for (int c = 0; c < 4; c++) {
                int ch = tid + c * 256;
                int row = ch >> 3, col = ch & 7;
                cpa16(sb + SMX(ps) + SWZ128(row * 128 + col * 16), xs + ch);
            }
            if (tid < 32) cpa16(sb + SMXX(ps) + tid * 16, g_xxp + t0 + 2 * NT + tid * 4);
        }
        CPA_COMMIT();         // always commit (possibly empty) to keep group count uniform

        // compute the 128-point stage as two 64-col halves
#pragma unroll
        for (int half = 0; half < 2; half++) {
            const int nh = half * 64 + nb;     // n-offset within stage (0..127)

            float d[2][4][4];
#pragma unroll
            for (int i = 0; i < 2; i++)
#pragma unroll
                for (int j = 0; j < 4; j++)
#pragma unroll
                    for (int k = 0; k < 4; k++) d[i][j][k] = 0.f;

#pragma unroll
            for (int ks = 0; ks < 4; ks++) {
                uint32_t b[4][2];
#pragma unroll
                for (int h = 0; h < 2; h++) {
                    uint32_t r[4];
                    uint32_t addr = sb + xb +
                        SWZ128((nh + h * 16 + b_row) * 128 + ks * 32 + b_kh * 16);
                    ldsm4(r, addr);
                    b[h * 2][0] = r[0]; b[h * 2][1] = r[1];
                    b[h * 2 + 1][0] = r[2]; b[h * 2 + 1][1] = r[3];
                }
#pragma unroll
                for (int mf = 0; mf < 2; mf++)
#pragma unroll
                    for (int nf = 0; nf < 4; nf++)
                        mma16816(d[mf][nf], &afr[ks][mf * 4], b[nf]);
            }

            // epilogue for this half
            const float* xxs = (const float*)(smem + xxb);
            float2 xv[4];
#pragma unroll
            for (int nf = 0; nf < 4; nf++) xv[nf] = *(const float2*)(xxs + nh + nf * 8 + tn2);

            const float* tsm = (const float*)(smem + SMTAU);
#pragma unroll
            for (int mf = 0; mf < 2; mf++) {
#pragma unroll
                for (int h = 0; h < 2; h++) {
                    const int gq = mtile * MT + m0 + mf * 16 + h * 8 + tq;
                    if (MODE == 0) {
                        unsigned short* dst = g_Du + (size_t)gq * SN + (t0 + nh + tn2);
#pragma unroll
                        for (int nf = 0; nf < 4; nf++) {
                            float v0 = d[mf][nf][h * 2] + xv[nf].x;
                            float v1 = d[mf][nf][h * 2 + 1] + xv[nf].y;
                            unsigned short u0 = f2bf(v0), u1 = f2bf(v1);
                            *(unsigned*)(dst + nf * 8) = (unsigned)u0 | ((unsigned)u1 << 16);
                        }
                    } else {
                        const float tau = tsm[m0 + mf * 16 + h * 8 + tq];
#pragma unroll
                        for (int nf = 0; nf < 4; nf++) {
                            float v0 = d[mf][nf][h * 2] + xv[nf].x;
                            float v1 = d[mf][nf][h * 2 + 1] + xv[nf].y;
                            if (v0 <= tau) {
                                int pos = atomicAdd(&g_cnt[gq], 1);
                                if (pos < CAP) g_si[(size_t)gq * CAP + pos] = t0 + nh + nf * 8 + tn2;
                            }
                            if (v1 <= tau) {
                                int pos = atomicAdd(&g_cnt[gq], 1);
                                if (pos < CAP) g_si[(size_t)gq * CAP + pos] = t0 + nh + nf * 8 + tn2 + 1;
                            }
                        }
                    }
                }
            }
        }
        // no trailing barrier: next iteration's barrier protects buffer reuse
    }
}

// ============================================================
// tau: radix-select 32nd smallest bf16 sample score + margin
// ============================================================
__global__ void tau_kernel() {
    __shared__ unsigned short sU[SN];
    __shared__ unsigned hist[256];
    __shared__ unsigned s_prefix;
    __shared__ int s_rank;
    const int b = blockIdx.x, tid = threadIdx.x;

    for (int i = tid; i < SN / 2; i += 256) {
        unsigned w = ((const unsigned*)(g_Du + (size_t)b * SN))[i];
        unsigned short u0 = (unsigned short)w, u1 = (unsigned short)(w >> 16);
        u0 = (u0 & 0x8000u) ? (unsigned short)~u0 : (unsigned short)(u0 | 0x8000u);
        u1 = (u1 & 0x8000u) ? (unsigned short)~u1 : (unsigned short)(u1 | 0x8000u);
        ((unsigned*)sU)[i] = (unsigned)u0 | ((unsigned)u1 << 16);
    }
    if (tid == 0) { s_prefix = 0u; s_rank = NK; }
    __syncthreads();

#pragma unroll
    for (int lev = 0; lev < 2; lev++) {
        const int sh = 8 - 8 * lev;
        hist[tid] = 0;
        __syncthreads();
        const unsigned pfx = s_prefix;
        for (int i = tid; i < SN; i += 256) {
            unsigned u = sU[i];
            if (lev == 0 || (u & 0xFF00u) == pfx)
                atomicAdd(&hist[(u >> sh) & 255u], 1u);
        }
        __syncthreads();
        if (tid == 0) {
            int r = s_rank;
            unsigned cum = 0;
            for (int k = 0; k < 256; k++) {
                unsigned h = hist[k];
                if (cum + h >= (unsigned)r) {
                    s_rank = r - (int)cum;
                    s_prefix = pfx | ((unsigned)k << sh);
                    break;
                }
                cum += h;
            }
        }
        __syncthreads();
    }
    if (tid == 0) {
        unsigned short u = (unsigned short)s_prefix;
        unsigned short bb = (u & 0x8000u) ? (unsigned short)(u ^ 0x8000u) : (unsigned short)~u;
        g_tau[b] = __uint_as_float((unsigned)bb << 16) + MARGIN;
    }
}

// ============================================================
// rescore: exact fp32 score per survivor (warp per survivor)
// ============================================================
__global__ void rescore_kernel(const float* __restrict__ xq, const float* __restrict__ Xd) {
    __shared__ float xs[NF];
    const int b = blockIdx.x, tid = threadIdx.x;
    if (tid < NF) xs[tid] = xq[(size_t)b * NF + tid];
    __syncthreads();
    int c = g_cnt[b]; if (c > CAP) c = CAP;
    const int w = tid >> 5, lane = tid & 31;
    float2 xv = *(const float2*)(xs + 2 * lane);
    for (int s = w; s < c; s += 8) {
        int n = g_si[(size_t)b * CAP + s];
        float2 Xv = *(const float2*)(Xd + (size_t)n * NF + 2 * lane);
        float p = xv.x * Xv.x + xv.y * Xv.y;
#pragma unroll
        for (int off = 16; off > 0; off >>= 1) p += __shfl_xor_sync(0xffffffffu, p, off);
        if (lane == 0) g_sv[(size_t)b * CAP + s] = g_xxp[n] - 2.f * p;
    }
}

// ============================================================
// select: exact top-32 from survivors, (val, idx) tie-break
// ============================================================
__global__ void select_kernel() {
    __shared__ float sv[CAP];
    __shared__ int si[CAP];
    __shared__ float rv[8];
    __shared__ int ri[8], rp[8];
    const int b = blockIdx.x, tid = threadIdx.x;
    int c = g_cnt[b]; if (c > CAP) c = CAP;
    const int cpad = (c + 255) & ~255;
    for (int i = tid; i < cpad; i += 256) {
        sv[i] = (i < c) ? g_sv[(size_t)b * CAP + i] : BIGV;
        si[i] = (i < c) ? g_si[(size_t)b * CAP + i] : 0x7FFFFFFF;
    }
    __syncthreads();
    for (int r = 0; r < NK; r++) {
        float bv = BIGV; int bi = 0x7FFFFFFF; int bp = 0;
        for (int i = tid; i < cpad; i += 256) {
            float v = sv[i]; int ix = si[i];
            if (v < bv || (v == bv && ix < bi)) { bv = v; bi = ix; bp = i; }
        }
#pragma unroll
        for (int off = 16; off > 0; off >>= 1) {
            float ov = __shfl_down_sync(0xffffffffu, bv, off);
            int oi = __shfl_down_sync(0xffffffffu, bi, off);
            int op = __shfl_down_sync(0xffffffffu, bp, off);
            if (ov < bv || (ov == bv && oi < bi)) { bv = ov; bi = oi; bp = op; }
        }
        if ((tid & 31) == 0) { rv[tid >> 5] = bv; ri[tid >> 5] = bi; rp[tid >> 5] = bp; }
        __syncthreads();
        if (tid == 0) {
            for (int wi = 1; wi < 8; wi++)
                if (rv[wi] < rv[0] || (rv[wi] == rv[0] && ri[wi] < ri[0])) {
                    rv[0] = rv[wi]; ri[0] = ri[wi]; rp[0] = rp[wi];
                }
            g_topk[b * NK + r] = ri[0];
            sv[rp[0]] = BIGV; si[rp[0]] = 0x7FFFFFFF;
        }
        __syncthreads();
    }
}

// ============================================================
// mlp: gather neighbors + gated MLP head (one block per query)
// ============================================================
__global__ void mlp_kernel(const float* __restrict__ xq, const float* __restrict__ Xd,
                           const float* __restrict__ yv, const float* __restrict__ Wg,
                           const float* __restrict__ bg, const float* __restrict__ W1,
                           const float* __restrict__ b1, const float* __restrict__ Wl,
                           const float* __restrict__ bl, float* __restrict__ out) {
    __shared__ float nfs[NK * 65];
    __shared__ float Wgs[65 * NC];
    __shared__ float gs[NK * NC];
    __shared__ float xa[NF + NC];
    __shared__ float red[4];
    __shared__ int idx[NK];
    const int b = blockIdx.x, tid = threadIdx.x;

    if (tid < NK) idx[tid] = g_topk[b * NK + tid];
    for (int i = tid; i < 65 * NC; i += 128) Wgs[i] = Wg[i];
    __syncthreads();
    for (int i = tid; i < NK * NF; i += 128) {
        int k = i >> 6, f = i & 63;
        nfs[k * 65 + f] = Xd[(size_t)idx[k] * NF + f];
    }
    if (tid < NK) nfs[tid * 65 + 64] = yv[idx[tid]];
    __syncthreads();

    {
        int k = tid & 31, c0 = (tid >> 5) * 4;
        float a0 = bg[c0], a1 = bg[c0 + 1], a2 = bg[c0 + 2], a3 = bg[c0 + 3];
#pragma unroll 5
        for (int j = 0; j < 65; j++) {
            float v = nfs[k * 65 + j];
            a0 += v * Wgs[j * NC + c0];
            a1 += v * Wgs[j * NC + c0 + 1];
            a2 += v * Wgs[j * NC + c0 + 2];
            a3 += v * Wgs[j * NC + c0 + 3];
        }
        gs[k * NC + c0] = tanhf(a0);
        gs[k * NC + c0 + 1] = tanhf(a1);
        gs[k * NC + c0 + 2] = tanhf(a2);
        gs[k * NC + c0 + 3] = tanhf(a3);
    }
    __syncthreads();
    if (tid < NF) {
        xa[tid] = xq[(size_t)b * NF + tid];
    } else if (tid < NF + NC) {
        int c = tid - NF;
        float s = 0.f;
#pragma unroll
        for (int k = 0; k < NK; k++) s += gs[k * NC + c];
        xa[tid] = s;
    }
    __syncthreads();

    float s = b1[tid];
#pragma unroll 8
    for (int i = 0; i < NF + NC; i++) s += xa[i] * W1[i * NH + tid];
    float oh = tanhf(s);
    float r = oh * Wl[tid];
#pragma unroll
    for (int off = 16; off > 0; off >>= 1) r += __shfl_down_sync(0xffffffffu, r, off);
    if ((tid & 31) == 0) red[tid >> 5] = r;
    __syncthreads();
    if (tid == 0) {
        float t = red[0] + red[1] + red[2] + red[3] + bl[0];
        out[b] = 1.f / (1.f + expf(-t));
    }
}

// ============================================================
extern "C" void kernel_launch(void* const* d_in, const int* in_sizes, int n_in,
                              void* d_out, int out_size) {
    (void)in_sizes; (void)n_in; (void)out_size;
    const float* xq = (const float*)d_in[0];
    const float* Xd = (const float*)d_in[1];
    const float* yv = (const float*)d_in[2];
    const float* Wg = (const float*)d_in[3];
    const float* bg = (const float*)d_in[4];
    const float* W1 = (const float*)d_in[5];
    const float* b1 = (const float*)d_in[6];
    const float* Wl = (const float*)d_in[7];
    const float* bl = (const float*)d_in[8];
    float* out = (float*)d_out;

    cudaFuncSetAttribute(mma_kernel<0, SAMPLE_TILES>, cudaFuncAttributeMaxDynamicSharedMemorySize, SM_TOTAL);
    cudaFuncSetAttribute(mma_kernel<1, MAIN_TILES>, cudaFuncAttributeMaxDynamicSharedMemorySize, SM_TOTAL);

    prep_x_kernel<<<NDPAD / 64, 256>>>(Xd);
    prep_q_kernel<<<128, 256>>>(xq);
    zero_kernel<<<4, 256>>>();
    mma_kernel<0, SAMPLE_TILES><<<dim3(NQ / MT, SAMPLE_SLICES), 256, SM_TOTAL>>>();
    tau_kernel<<<NQ, 256>>>();
    mma_kernel<1, MAIN_TILES><<<dim3(NQ / MT, NSL), 256, SM_TOTAL>>>();
    rescore_kernel<<<NQ, 256>>>(xq, Xd);
    select_kernel<<<NQ, 256>>>();
    mlp_kernel<<<NQ, 128>>>(xq, Xd, yv, Wg, bg, W1, b1, Wl, bl, out);
}